// round 5
// baseline (speedup 1.0000x reference)
#include <cuda_runtime.h>
#include <cuda_bf16.h>
#include <cstdint>

#define HC 100
typedef unsigned long long ull;

__device__ float g_nproj[(size_t)100000 * 400];
__device__ float g_acc[(size_t)100000 * HC];
__device__ float g_denom[(size_t)100000 * 2];

__device__ __forceinline__ void ffma2(ull &acc, ull a, ull b) {
    asm("fma.rn.f32x2 %0, %1, %2, %0;" : "+l"(acc) : "l"(a), "l"(b));
}
__device__ __forceinline__ ull pack2(float x, float y) {
    ull r; asm("mov.b64 %0, {%1, %2};" : "=l"(r) : "f"(x), "f"(y)); return r;
}
__device__ __forceinline__ float2 unpack2(ull v) {
    float2 f; asm("mov.b64 {%0, %1}, %2;" : "=f"(f.x), "=f"(f.y) : "l"(v)); return f;
}
__device__ __forceinline__ void red2(float* p, float a, float b) {
    asm volatile("red.global.add.v2.f32 [%0], {%1, %2};" :: "l"(p), "f"(a), "f"(b) : "memory");
}
__device__ __forceinline__ void red4(float* p, float a, float b, float c, float d) {
    asm volatile("red.global.add.v4.f32 [%0], {%1, %2, %3, %4};"
                 :: "l"(p), "f"(a), "f"(b), "f"(c), "f"(d) : "memory");
}
__device__ __forceinline__ void prefetchL2(const void* p) {
    asm volatile("prefetch.global.L2 [%0];" :: "l"(p));
}
__device__ __forceinline__ uint32_t smem_u32(const void* p) {
    uint32_t a;
    asm("{ .reg .u64 t; cvta.to.shared.u64 t, %1; cvt.u32.u64 %0, t; }" : "=r"(a) : "l"(p));
    return a;
}
__device__ __forceinline__ void ldsm_x4(uint32_t* r, uint32_t a) {
    asm volatile("ldmatrix.sync.aligned.m8n8.x4.shared.b16 {%0,%1,%2,%3}, [%4];"
                 : "=r"(r[0]), "=r"(r[1]), "=r"(r[2]), "=r"(r[3]) : "r"(a));
}
__device__ __forceinline__ void ldsm_x2(uint32_t* r, uint32_t a) {
    asm volatile("ldmatrix.sync.aligned.m8n8.x2.shared.b16 {%0,%1}, [%2];"
                 : "=r"(r[0]), "=r"(r[1]) : "r"(a));
}
__device__ __forceinline__ void mma16816(float* c, const uint32_t* a, const uint32_t* b) {
    asm volatile("mma.sync.aligned.m16n8k16.row.col.f32.bf16.bf16.f32 "
                 "{%0,%1,%2,%3}, {%4,%5,%6,%7}, {%8,%9}, {%0,%1,%2,%3};"
                 : "+f"(c[0]), "+f"(c[1]), "+f"(c[2]), "+f"(c[3])
                 : "r"(a[0]), "r"(a[1]), "r"(a[2]), "r"(a[3]), "r"(b[0]), "r"(b[1]));
}

// cos(2*pi*t) via FMA-pipe polynomial (no MUFU). |err| <~ 2e-6.
__device__ __forceinline__ float cos2pi(float t) {
    t -= rintf(t);                 // t in [-0.5, 0.5]
    float u = t * t;
    float p = fmaf(u, 0.2820435f, -1.7143716f);
    p = fmaf(u, p, 7.9035540f);
    p = fmaf(u, p, -26.4262337f);
    p = fmaf(u, p, 60.2446352f);
    p = fmaf(u, p, -85.4568172f);
    p = fmaf(u, p, 64.9393940f);
    p = fmaf(u, p, -19.7392088f);
    return fmaf(u, p, 1.0f);
}

// ---------------------------------------------------------------------------
__global__ void k_zero(int n) {
    int na = n * 25;
    int tot = na + n;
    float4 z4 = make_float4(0.f, 0.f, 0.f, 0.f);
    for (int i = blockIdx.x * blockDim.x + threadIdx.x; i < tot;
         i += gridDim.x * blockDim.x) {
        if (i < na) ((float4*)g_acc)[i] = z4;
        else        ((float2*)g_denom)[i - na] = make_float2(0.f, 0.f);
    }
}

// ---------------------------------------------------------------------------
// Node projections (FFMA2 version, proven in R2)
// ---------------------------------------------------------------------------
__global__ void __launch_bounds__(384, 1) k_nproj(
    const float* __restrict__ x,
    const float* __restrict__ Wq, const float* __restrict__ bq,
    const float* __restrict__ Wk, const float* __restrict__ bk,
    const float* __restrict__ Wv, const float* __restrict__ bv,
    const float* __restrict__ Ws, const float* __restrict__ bs,
    int n)
{
    extern __shared__ float sm[];
    float* wsm  = sm;
    float* bsm  = sm + 40000;
    float* actb = sm + 40400;

    int tid = threadIdx.x;
    for (int i = tid; i < 40000; i += 384) {
        int k = i / 400, c = i % 400;
        float v;
        if      (c < 100) v = Wq[k * 100 + c];
        else if (c < 200) v = Wk[k * 100 + c - 100];
        else if (c < 300) v = Wv[k * 100 + c - 200];
        else              v = Ws[k * 100 + c - 300];
        wsm[i] = v;
    }
    for (int i = tid; i < 400; i += 384) {
        bsm[i] = (i < 100) ? bq[i] : (i < 200) ? bk[i - 100]
               : (i < 300) ? bv[i - 200] : bs[i - 300];
    }
    __syncthreads();

    int warp = tid >> 5, lane = tid & 31;
    int gwarp = blockIdx.x * 12 + warp;
    int nwarps = gridDim.x * 12;
    float* aw = actb + warp * 400;
    int lq = (lane < 25) ? lane : 24;

    int nblocks = (n + 3) >> 2;
    for (int blk = gwarp; blk < nblocks; blk += nwarps) {
        int nbase = blk * 4;
        __syncwarp();
        #pragma unroll
        for (int e = 0; e < 4; e++) {
            int nd = nbase + e; if (nd >= n) nd = n - 1;
            if (lane < 25)
                ((float4*)(aw + e * 100))[lane] =
                    ((const float4*)(x + (size_t)nd * 100))[lane];
        }
        __syncwarp();

        ull acc[4][4][2];
        #pragma unroll
        for (int g = 0; g < 4; g++) {
            ulonglong2 b2 = *(const ulonglong2*)(bsm + g * 100 + lq * 4);
            #pragma unroll
            for (int e = 0; e < 4; e++) { acc[e][g][0] = b2.x; acc[e][g][1] = b2.y; }
        }

        #pragma unroll 1
        for (int k = 0; k < 100; k += 2) {
            ull ad[4][2];
            #pragma unroll
            for (int e = 0; e < 4; e++) {
                float2 a2 = *(const float2*)(aw + e * 100 + k);
                ad[e][0] = pack2(a2.x, a2.x);
                ad[e][1] = pack2(a2.y, a2.y);
            }
            #pragma unroll
            for (int g = 0; g < 4; g++) {
                ulonglong2 w0 = *(const ulonglong2*)(wsm + k * 400 + g * 100 + lq * 4);
                ulonglong2 w1 = *(const ulonglong2*)(wsm + (k + 1) * 400 + g * 100 + lq * 4);
                #pragma unroll
                for (int e = 0; e < 4; e++) {
                    ffma2(acc[e][g][0], ad[e][0], w0.x);
                    ffma2(acc[e][g][1], ad[e][0], w0.y);
                    ffma2(acc[e][g][0], ad[e][1], w1.x);
                    ffma2(acc[e][g][1], ad[e][1], w1.y);
                }
            }
        }

        #pragma unroll
        for (int e = 0; e < 4; e++) {
            int nd = nbase + e;
            if (nd < n && lane < 25) {
                #pragma unroll
                for (int g = 0; g < 4; g++) {
                    float2 lo = unpack2(acc[e][g][0]);
                    float2 hi = unpack2(acc[e][g][1]);
                    *(float4*)(g_nproj + (size_t)nd * 400 + g * 100 + lq * 4) =
                        make_float4(lo.x, lo.y, hi.x, hi.y);
                }
            }
        }
        __syncwarp();
    }
}

// ---------------------------------------------------------------------------
// Edge kernel: HMMA (mma.sync m16n8k16 bf16) split GEMM
//   D[128 edges, 104] = A[128,272] * WeT[104,272]
// ---------------------------------------------------------------------------
#define SM_WHI 0
#define SM_WLO 58240
#define SM_A   116480
#define SM_SRC 188160
#define SM_DST 188672
#define SM_REL 189184
#define SM_WTB 189696
#define SMEM_EDGE_BYTES 190496

__device__ __forceinline__ void build_tile(
    char* smb, const float* __restrict__ msg, int ebase, int ne, int tid, int lopass)
{
    const float* wtb = (const float*)(smb + SM_WTB);   // Wt/2pi | bt/2pi
    const float* rel = (const float*)(smb + SM_REL);
    for (int idx = tid; idx < 4352; idx += 384) {
        int r = idx / 34, g = idx - r * 34;
        int j0 = g * 8;
        int eg = ebase + r; if (eg >= ne) eg = ne - 1;
        float v[8];
        if (j0 + 8 <= 100) {
            float rr = rel[r];
            #pragma unroll
            for (int i = 0; i < 8; i++)
                v[i] = cos2pi(fmaf(rr, wtb[j0 + i], wtb[100 + j0 + i]));
        } else if (j0 >= 104) {
            const float4* m4 = (const float4*)(msg + (size_t)eg * 172 + (j0 - 100));
            float4 a = m4[0], b = m4[1];
            v[0] = a.x; v[1] = a.y; v[2] = a.z; v[3] = a.w;
            v[4] = b.x; v[5] = b.y; v[6] = b.z; v[7] = b.w;
        } else {
            float rr = rel[r];
            const float* mrow = msg + (size_t)eg * 172;
            #pragma unroll
            for (int i = 0; i < 8; i++) {
                int j = j0 + i;
                v[i] = (j < 100) ? cos2pi(fmaf(rr, wtb[j], wtb[100 + j])) : mrow[j - 100];
            }
        }
        if (lopass) {
            #pragma unroll
            for (int i = 0; i < 8; i++)
                v[i] -= __bfloat162float(__float2bfloat16(v[i]));
        }
        uint32_t p[4];
        #pragma unroll
        for (int i = 0; i < 4; i++) {
            __nv_bfloat162 h;
            h.x = __float2bfloat16(v[2 * i]);
            h.y = __float2bfloat16(v[2 * i + 1]);
            p[i] = *reinterpret_cast<uint32_t*>(&h);
        }
        *(uint4*)(smb + SM_A + r * 560 + j0 * 2) = make_uint4(p[0], p[1], p[2], p[3]);
    }
}

__global__ void __launch_bounds__(384, 1) k_edge(
    const float* __restrict__ lu, const float* __restrict__ t,
    const float* __restrict__ msg,
    const float* __restrict__ Wt, const float* __restrict__ bt,
    const float* __restrict__ We, const int* __restrict__ ei,
    int n, int ne)
{
    extern __shared__ char smb[];
    uint32_t sbase = smem_u32(smb);
    int tid = threadIdx.x;
    int warp = tid >> 5, lane = tid & 31;

    for (int idx = tid; idx < 104 * 272; idx += 384) {
        int c = idx / 272, j = idx - c * 272;
        float w = (c < 100) ? We[j * 100 + c] : 0.0f;
        __nv_bfloat16 h = __float2bfloat16(w);
        float lf = w - __bfloat162float(h);
        *(__nv_bfloat16*)(smb + SM_WHI + c * 560 + j * 2) = h;
        *(__nv_bfloat16*)(smb + SM_WLO + c * 560 + j * 2) = __float2bfloat16(lf);
    }
    {
        const float INV2PI = 0.15915494309189535f;
        float* wtb = (float*)(smb + SM_WTB);
        for (int i = tid; i < 100; i += 384) {
            wtb[i]       = Wt[i] * INV2PI;
            wtb[100 + i] = bt[i] * INV2PI;
        }
    }
    __syncthreads();

    int* s_src = (int*)(smb + SM_SRC);
    int* s_dst = (int*)(smb + SM_DST);
    float* s_rel = (float*)(smb + SM_REL);
    float* es = (float*)(smb + SM_A);   // es[104][129] overlays A after MMA
    const float SCALE = 0.14142135623730951f;
    int lq = (lane < 25) ? lane : 24;

    int ntiles = (ne + 127) >> 7;
    for (int tile = blockIdx.x; tile < ntiles; tile += gridDim.x) {
        int ebase = tile << 7;
        __syncthreads();

        if (tid < 128) {
            int eg = ebase + tid;
            bool valid = eg < ne;
            int eidx = valid ? eg : 0;
            int s = ei[eidx], d = ei[ne + eidx];
            s_src[tid] = s; s_dst[tid] = d;
            s_rel[tid] = valid ? (lu[s] - t[eidx]) : 0.0f;
            if (valid) {
                const char* qb = (const char*)(g_nproj + (size_t)d * 400);
                const char* kb = (const char*)(g_nproj + (size_t)s * 400 + 100);
                const char* vb = (const char*)(g_nproj + (size_t)s * 400 + 200);
                #pragma unroll
                for (int o = 0; o < 400; o += 128) {
                    prefetchL2(qb + o); prefetchL2(kb + o); prefetchL2(vb + o);
                }
            }
        }
        __syncthreads();

        build_tile(smb, msg, ebase, ne, tid, 0);   // A-hi
        __syncthreads();

        float acc[13][4];
        #pragma unroll
        for (int nf = 0; nf < 13; nf++) {
            acc[nf][0] = 0.f; acc[nf][1] = 0.f; acc[nf][2] = 0.f; acc[nf][3] = 0.f;
        }

        if (warp < 8) {
            int r0 = warp * 16;
            uint32_t abase = sbase + SM_A
                           + (uint32_t)((r0 + (lane & 15)) * 560 + (lane >> 4) * 16);
            uint32_t af[17][4];
            #pragma unroll
            for (int k = 0; k < 17; k++) ldsm_x4(af[k], abase + k * 32);

            #pragma unroll
            for (int nf = 0; nf < 13; nf++) {
                uint32_t bhb = sbase + SM_WHI
                    + (uint32_t)((nf * 8 + (lane & 7)) * 560 + (lane >> 3) * 16);
                uint32_t blb = bhb + (SM_WLO - SM_WHI);
                #pragma unroll
                for (int kk = 0; kk < 8; kk++) {
                    uint32_t bh[4], bl[4];
                    ldsm_x4(bh, bhb + kk * 64);
                    ldsm_x4(bl, blb + kk * 64);
                    mma16816(acc[nf], af[2 * kk],     bh);
                    mma16816(acc[nf], af[2 * kk],     bl);
                    mma16816(acc[nf], af[2 * kk + 1], bh + 2);
                    mma16816(acc[nf], af[2 * kk + 1], bl + 2);
                }
                uint32_t b2h[2], b2l[2];
                ldsm_x2(b2h, bhb + 512);
                ldsm_x2(b2l, blb + 512);
                mma16816(acc[nf], af[16], b2h);
                mma16816(acc[nf], af[16], b2l);
            }
        }
        __syncthreads();

        build_tile(smb, msg, ebase, ne, tid, 1);   // A-lo
        __syncthreads();

        if (warp < 8) {
            int r0 = warp * 16;
            uint32_t abase = sbase + SM_A
                           + (uint32_t)((r0 + (lane & 15)) * 560 + (lane >> 4) * 16);
            uint32_t af[17][4];
            #pragma unroll
            for (int k = 0; k < 17; k++) ldsm_x4(af[k], abase + k * 32);

            #pragma unroll
            for (int nf = 0; nf < 13; nf++) {
                uint32_t bhb = sbase + SM_WHI
                    + (uint32_t)((nf * 8 + (lane & 7)) * 560 + (lane >> 3) * 16);
                #pragma unroll
                for (int kk = 0; kk < 8; kk++) {
                    uint32_t bh[4];
                    ldsm_x4(bh, bhb + kk * 64);
                    mma16816(acc[nf], af[2 * kk],     bh);
                    mma16816(acc[nf], af[2 * kk + 1], bh + 2);
                }
                uint32_t b2h[2];
                ldsm_x2(b2h, bhb + 512);
                mma16816(acc[nf], af[16], b2h);
            }
        }
        __syncthreads();

        if (warp < 8) {
            int r0 = warp * 16;
            int rowA = r0 + (lane >> 2);
            #pragma unroll
            for (int nf = 0; nf < 13; nf++) {
                int col = nf * 8 + 2 * (lane & 3);
                es[col * 129 + rowA]           = acc[nf][0];
                es[(col + 1) * 129 + rowA]     = acc[nf][1];
                es[col * 129 + rowA + 8]       = acc[nf][2];
                es[(col + 1) * 129 + rowA + 8] = acc[nf][3];
            }
        }
        __syncthreads();

        #pragma unroll 1
        for (int er = warp; er < 128; er += 12) {
            int eg = ebase + er;
            if (eg >= ne) break;
            int s = s_src[er], d = s_dst[er];
            float ec0 = 0.f, ec1 = 0.f, ec2 = 0.f, ec3 = 0.f, d0 = 0.f, d1 = 0.f;
            float4 qv = make_float4(0,0,0,0), kv = qv, vv = qv;
            if (lane < 25) {
                ec0 = es[(4 * lq + 0) * 129 + er];
                ec1 = es[(4 * lq + 1) * 129 + er];
                ec2 = es[(4 * lq + 2) * 129 + er];
                ec3 = es[(4 * lq + 3) * 129 + er];
                qv = *(const float4*)(g_nproj + (size_t)d * 400 + lq * 4);
                kv = *(const float4*)(g_nproj + (size_t)s * 400 + 100 + lq * 4);
                vv = *(const float4*)(g_nproj + (size_t)s * 400 + 200 + lq * 4);
                d0 = qv.x * (kv.x + ec0) + qv.y * (kv.y + ec1);
                d1 = qv.z * (kv.z + ec2) + qv.w * (kv.w + ec3);
            }
            float p0 = ((lane < 13) ? d0 : 0.0f) + ((lane < 12) ? d1 : 0.0f);
            float p1 = ((lane < 13) ? 0.0f : d0) + ((lane < 12) ? 0.0f : d1);
            #pragma unroll
            for (int o = 16; o > 0; o >>= 1) {
                p0 += __shfl_xor_sync(0xffffffffu, p0, o);
                p1 += __shfl_xor_sync(0xffffffffu, p1, o);
            }
            float ex0 = __expf(p0 * SCALE);
            float ex1 = __expf(p1 * SCALE);
            if (lane == 0) red2(&g_denom[(size_t)d * 2], ex0, ex1);
            if (lane < 25) {
                float w0 = (lane < 13) ? ex0 : ex1;
                float w1 = (lane < 12) ? ex0 : ex1;
                red4(g_acc + (size_t)d * 100 + lq * 4,
                     w0 * (vv.x + ec0), w0 * (vv.y + ec1),
                     w1 * (vv.z + ec2), w1 * (vv.w + ec3));
            }
        }
    }
}

// ---------------------------------------------------------------------------
__global__ void k_final(float* __restrict__ out, int n) {
    int tot = n * 25;
    for (int i = blockIdx.x * blockDim.x + threadIdx.x; i < tot;
         i += gridDim.x * blockDim.x) {
        int nd = i / 25, q = i % 25;
        float den0 = g_denom[(size_t)nd * 2 + 0];
        float den1 = g_denom[(size_t)nd * 2 + 1];
        float dxy = (q < 13) ? den0 : den1;
        float dzw = (q < 12) ? den0 : den1;
        float rxy = (dxy > 0.0f) ? (1.0f / dxy) : 0.0f;
        float rzw = (dzw > 0.0f) ? (1.0f / dzw) : 0.0f;
        float4 a4 = ((const float4*)g_acc)[i];
        float4 sk = *(const float4*)(g_nproj + (size_t)nd * 400 + 300 + q * 4);
        float4 o;
        o.x = a4.x * rxy + sk.x;
        o.y = a4.y * rxy + sk.y;
        o.z = a4.z * rzw + sk.z;
        o.w = a4.w * rzw + sk.w;
        ((float4*)out)[i] = o;
    }
}

// ---------------------------------------------------------------------------
extern "C" void kernel_launch(void* const* d_in, const int* in_sizes, int n_in,
                              void* d_out, int out_size) {
    const float* x   = (const float*)d_in[0];
    const float* lu  = (const float*)d_in[1];
    const float* t   = (const float*)d_in[2];
    const float* msg = (const float*)d_in[3];
    const float* Wt  = (const float*)d_in[4];
    const float* bt  = (const float*)d_in[5];
    const float* Wq  = (const float*)d_in[6];
    const float* bq  = (const float*)d_in[7];
    const float* Wk  = (const float*)d_in[8];
    const float* bk  = (const float*)d_in[9];
    const float* Wv  = (const float*)d_in[10];
    const float* bv  = (const float*)d_in[11];
    const float* We  = (const float*)d_in[12];
    const float* Ws  = (const float*)d_in[13];
    const float* bs  = (const float*)d_in[14];
    const int*   ei  = (const int*)d_in[15];

    int n  = in_sizes[1];
    int ne = in_sizes[2];
    float* out = (float*)d_out;

    int dev = 0;
    cudaGetDevice(&dev);
    int nsm = 148;
    cudaDeviceGetAttribute(&nsm, cudaDevAttrMultiProcessorCount, dev);

    size_t smem1 = (size_t)(40000 + 400 + 12 * 400) * 4;
    cudaFuncSetAttribute(k_nproj, cudaFuncAttributeMaxDynamicSharedMemorySize, (int)smem1);
    cudaFuncSetAttribute(k_edge,  cudaFuncAttributeMaxDynamicSharedMemorySize, SMEM_EDGE_BYTES);

    k_zero<<<2048, 256>>>(n);
    k_nproj<<<nsm, 384, smem1>>>(x, Wq, bq, Wk, bk, Wv, bv, Ws, bs, n);
    k_edge<<<nsm, 384, SMEM_EDGE_BYTES>>>(lu, t, msg, Wt, bt, We, ei, n, ne);
    k_final<<<4096, 256>>>(out, n);
}

// round 6
// speedup vs baseline: 1.3035x; 1.3035x over previous
#include <cuda_runtime.h>
#include <cuda_fp16.h>
#include <cstdint>

#define HC 100
typedef unsigned long long ull;

__device__ float g_nproj[(size_t)100000 * 400];
__device__ float g_acc[(size_t)100000 * HC];
__device__ float g_denom[(size_t)100000 * 2];

__device__ __forceinline__ void ffma2(ull &acc, ull a, ull b) {
    asm("fma.rn.f32x2 %0, %1, %2, %0;" : "+l"(acc) : "l"(a), "l"(b));
}
__device__ __forceinline__ ull pack2(float x, float y) {
    ull r; asm("mov.b64 %0, {%1, %2};" : "=l"(r) : "f"(x), "f"(y)); return r;
}
__device__ __forceinline__ float2 unpack2(ull v) {
    float2 f; asm("mov.b64 {%0, %1}, %2;" : "=f"(f.x), "=f"(f.y) : "l"(v)); return f;
}
__device__ __forceinline__ void red2(float* p, float a, float b) {
    asm volatile("red.global.add.v2.f32 [%0], {%1, %2};" :: "l"(p), "f"(a), "f"(b) : "memory");
}
__device__ __forceinline__ void red4(float* p, float a, float b, float c, float d) {
    asm volatile("red.global.add.v4.f32 [%0], {%1, %2, %3, %4};"
                 :: "l"(p), "f"(a), "f"(b), "f"(c), "f"(d) : "memory");
}
__device__ __forceinline__ void prefetchL2(const void* p) {
    asm volatile("prefetch.global.L2 [%0];" :: "l"(p));
}
__device__ __forceinline__ uint32_t smem_u32(const void* p) {
    uint32_t a;
    asm("{ .reg .u64 t; cvta.to.shared.u64 t, %1; cvt.u32.u64 %0, t; }" : "=r"(a) : "l"(p));
    return a;
}
__device__ __forceinline__ void ldsm_x4(uint32_t* r, uint32_t a) {
    asm volatile("ldmatrix.sync.aligned.m8n8.x4.shared.b16 {%0,%1,%2,%3}, [%4];"
                 : "=r"(r[0]), "=r"(r[1]), "=r"(r[2]), "=r"(r[3]) : "r"(a));
}
__device__ __forceinline__ void ldsm_x2(uint32_t* r, uint32_t a) {
    asm volatile("ldmatrix.sync.aligned.m8n8.x2.shared.b16 {%0,%1}, [%2];"
                 : "=r"(r[0]), "=r"(r[1]) : "r"(a));
}
__device__ __forceinline__ void mma16816(float* c, const uint32_t* a, const uint32_t* b) {
    asm volatile("mma.sync.aligned.m16n8k16.row.col.f32.f16.f16.f32 "
                 "{%0,%1,%2,%3}, {%4,%5,%6,%7}, {%8,%9}, {%0,%1,%2,%3};"
                 : "+f"(c[0]), "+f"(c[1]), "+f"(c[2]), "+f"(c[3])
                 : "r"(a[0]), "r"(a[1]), "r"(a[2]), "r"(a[3]), "r"(b[0]), "r"(b[1]));
}

// ---------------------------------------------------------------------------
__global__ void k_zero(int n) {
    int na = n * 25;
    int tot = na + n;
    float4 z4 = make_float4(0.f, 0.f, 0.f, 0.f);
    for (int i = blockIdx.x * blockDim.x + threadIdx.x; i < tot;
         i += gridDim.x * blockDim.x) {
        if (i < na) ((float4*)g_acc)[i] = z4;
        else        ((float2*)g_denom)[i - na] = make_float2(0.f, 0.f);
    }
}

// ---------------------------------------------------------------------------
// Node projections (FFMA2 version, proven in R2)
// ---------------------------------------------------------------------------
__global__ void __launch_bounds__(384, 1) k_nproj(
    const float* __restrict__ x,
    const float* __restrict__ Wq, const float* __restrict__ bq,
    const float* __restrict__ Wk, const float* __restrict__ bk,
    const float* __restrict__ Wv, const float* __restrict__ bv,
    const float* __restrict__ Ws, const float* __restrict__ bs,
    int n)
{
    extern __shared__ float sm[];
    float* wsm  = sm;
    float* bsm  = sm + 40000;
    float* actb = sm + 40400;

    int tid = threadIdx.x;
    for (int i = tid; i < 40000; i += 384) {
        int k = i / 400, c = i % 400;
        float v;
        if      (c < 100) v = Wq[k * 100 + c];
        else if (c < 200) v = Wk[k * 100 + c - 100];
        else if (c < 300) v = Wv[k * 100 + c - 200];
        else              v = Ws[k * 100 + c - 300];
        wsm[i] = v;
    }
    for (int i = tid; i < 400; i += 384) {
        bsm[i] = (i < 100) ? bq[i] : (i < 200) ? bk[i - 100]
               : (i < 300) ? bv[i - 200] : bs[i - 300];
    }
    __syncthreads();

    int warp = tid >> 5, lane = tid & 31;
    int gwarp = blockIdx.x * 12 + warp;
    int nwarps = gridDim.x * 12;
    float* aw = actb + warp * 400;
    int lq = (lane < 25) ? lane : 24;

    int nblocks = (n + 3) >> 2;
    for (int blk = gwarp; blk < nblocks; blk += nwarps) {
        int nbase = blk * 4;
        __syncwarp();
        #pragma unroll
        for (int e = 0; e < 4; e++) {
            int nd = nbase + e; if (nd >= n) nd = n - 1;
            if (lane < 25)
                ((float4*)(aw + e * 100))[lane] =
                    ((const float4*)(x + (size_t)nd * 100))[lane];
        }
        __syncwarp();

        ull acc[4][4][2];
        #pragma unroll
        for (int g = 0; g < 4; g++) {
            ulonglong2 b2 = *(const ulonglong2*)(bsm + g * 100 + lq * 4);
            #pragma unroll
            for (int e = 0; e < 4; e++) { acc[e][g][0] = b2.x; acc[e][g][1] = b2.y; }
        }

        #pragma unroll 1
        for (int k = 0; k < 100; k += 2) {
            ull ad[4][2];
            #pragma unroll
            for (int e = 0; e < 4; e++) {
                float2 a2 = *(const float2*)(aw + e * 100 + k);
                ad[e][0] = pack2(a2.x, a2.x);
                ad[e][1] = pack2(a2.y, a2.y);
            }
            #pragma unroll
            for (int g = 0; g < 4; g++) {
                ulonglong2 w0 = *(const ulonglong2*)(wsm + k * 400 + g * 100 + lq * 4);
                ulonglong2 w1 = *(const ulonglong2*)(wsm + (k + 1) * 400 + g * 100 + lq * 4);
                #pragma unroll
                for (int e = 0; e < 4; e++) {
                    ffma2(acc[e][g][0], ad[e][0], w0.x);
                    ffma2(acc[e][g][1], ad[e][0], w0.y);
                    ffma2(acc[e][g][0], ad[e][1], w1.x);
                    ffma2(acc[e][g][1], ad[e][1], w1.y);
                }
            }
        }

        #pragma unroll
        for (int e = 0; e < 4; e++) {
            int nd = nbase + e;
            if (nd < n && lane < 25) {
                #pragma unroll
                for (int g = 0; g < 4; g++) {
                    float2 lo = unpack2(acc[e][g][0]);
                    float2 hi = unpack2(acc[e][g][1]);
                    *(float4*)(g_nproj + (size_t)nd * 400 + g * 100 + lq * 4) =
                        make_float4(lo.x, lo.y, hi.x, hi.y);
                }
            }
        }
        __syncwarp();
    }
}

// ---------------------------------------------------------------------------
// Edge kernel: HMMA fp16 2-pass split GEMM
//   D[128 edges, 104] = A[128,272] * (Whi + Wlo)T ; A single fp16, W split fp16
// ---------------------------------------------------------------------------
#define SM_WHI 0
#define SM_WLO 58240
#define SM_A   116480
#define SM_SRC 188160
#define SM_DST 188672
#define SM_REL 189184
#define SM_WTB 189696
#define SMEM_EDGE_BYTES 190496

__device__ __forceinline__ void build_tile(
    char* smb, const float* __restrict__ msg, int ebase, int ne, int tid)
{
    const float* wtb = (const float*)(smb + SM_WTB);   // Wt | bt
    const float* rel = (const float*)(smb + SM_REL);
    for (int idx = tid; idx < 4352; idx += 384) {
        int r = idx / 34, g = idx - r * 34;
        int j0 = g * 8;
        int eg = ebase + r; if (eg >= ne) eg = ne - 1;
        float v[8];
        if (j0 + 8 <= 100) {
            float rr = rel[r];
            #pragma unroll
            for (int i = 0; i < 8; i++)
                v[i] = __cosf(fmaf(rr, wtb[j0 + i], wtb[100 + j0 + i]));
        } else if (j0 >= 104) {
            const float4* m4 = (const float4*)(msg + (size_t)eg * 172 + (j0 - 100));
            float4 a = m4[0], b = m4[1];
            v[0] = a.x; v[1] = a.y; v[2] = a.z; v[3] = a.w;
            v[4] = b.x; v[5] = b.y; v[6] = b.z; v[7] = b.w;
        } else {
            float rr = rel[r];
            const float* mrow = msg + (size_t)eg * 172;
            #pragma unroll
            for (int i = 0; i < 8; i++) {
                int j = j0 + i;
                v[i] = (j < 100) ? __cosf(fmaf(rr, wtb[j], wtb[100 + j])) : mrow[j - 100];
            }
        }
        uint32_t p[4];
        #pragma unroll
        for (int i = 0; i < 4; i++) {
            __half2 h;
            h.x = __float2half_rn(v[2 * i]);
            h.y = __float2half_rn(v[2 * i + 1]);
            p[i] = *reinterpret_cast<uint32_t*>(&h);
        }
        *(uint4*)(smb + SM_A + r * 560 + j0 * 2) = make_uint4(p[0], p[1], p[2], p[3]);
    }
}

__global__ void __launch_bounds__(384, 1) k_edge(
    const float* __restrict__ lu, const float* __restrict__ t,
    const float* __restrict__ msg,
    const float* __restrict__ Wt, const float* __restrict__ bt,
    const float* __restrict__ We, const int* __restrict__ ei,
    int n, int ne)
{
    extern __shared__ char smb[];
    uint32_t sbase = smem_u32(smb);
    int tid = threadIdx.x;
    int warp = tid >> 5, lane = tid & 31;

    // one-time: W hi/lo [104 n-rows][272 k] fp16, stride 280; cols>=100 zero
    for (int idx = tid; idx < 104 * 272; idx += 384) {
        int c = idx / 272, j = idx - c * 272;
        float w = (c < 100) ? We[j * 100 + c] : 0.0f;
        __half h = __float2half_rn(w);
        float lf = w - __half2float(h);
        *(__half*)(smb + SM_WHI + c * 560 + j * 2) = h;
        *(__half*)(smb + SM_WLO + c * 560 + j * 2) = __float2half_rn(lf);
    }
    {
        float* wtb = (float*)(smb + SM_WTB);
        for (int i = tid; i < 100; i += 384) { wtb[i] = Wt[i]; wtb[100 + i] = bt[i]; }
    }
    __syncthreads();

    int* s_src = (int*)(smb + SM_SRC);
    int* s_dst = (int*)(smb + SM_DST);
    float* s_rel = (float*)(smb + SM_REL);
    float* es = (float*)(smb + SM_A);   // es[104][129] overlays A after MMA
    const float SCALE = 0.14142135623730951f;
    int lq = (lane < 25) ? lane : 24;

    int ntiles = (ne + 127) >> 7;
    for (int tile = blockIdx.x; tile < ntiles; tile += gridDim.x) {
        int ebase = tile << 7;
        __syncthreads();   // prev epilogue done before overwriting es/A/meta

        if (tid < 128) {
            int eg = ebase + tid;
            bool valid = eg < ne;
            int eidx = valid ? eg : 0;
            int s = ei[eidx], d = ei[ne + eidx];
            s_src[tid] = s; s_dst[tid] = d;
            s_rel[tid] = valid ? (lu[s] - t[eidx]) : 0.0f;
            if (valid) {
                const char* qb = (const char*)(g_nproj + (size_t)d * 400);
                const char* kb = (const char*)(g_nproj + (size_t)s * 400 + 100);
                const char* vb = (const char*)(g_nproj + (size_t)s * 400 + 200);
                #pragma unroll
                for (int o = 0; o < 400; o += 128) {
                    prefetchL2(qb + o); prefetchL2(kb + o); prefetchL2(vb + o);
                }
            }
        }
        __syncthreads();

        build_tile(smb, msg, ebase, ne, tid);   // A (single fp16)
        __syncthreads();

        float acc[13][4];
        #pragma unroll
        for (int nf = 0; nf < 13; nf++) {
            acc[nf][0] = 0.f; acc[nf][1] = 0.f; acc[nf][2] = 0.f; acc[nf][3] = 0.f;
        }

        if (warp < 8) {
            int r0 = warp * 16;
            uint32_t abase = sbase + SM_A
                           + (uint32_t)((r0 + (lane & 15)) * 560 + (lane >> 4) * 16);
            uint32_t af[17][4];
            #pragma unroll
            for (int k = 0; k < 17; k++) ldsm_x4(af[k], abase + k * 32);

            // fused: A*Whi + A*Wlo
            #pragma unroll
            for (int nf = 0; nf < 13; nf++) {
                uint32_t bhb = sbase + SM_WHI
                    + (uint32_t)((nf * 8 + (lane & 7)) * 560 + (lane >> 3) * 16);
                uint32_t blb = bhb + (SM_WLO - SM_WHI);
                #pragma unroll
                for (int kk = 0; kk < 8; kk++) {
                    uint32_t bh[4], bl[4];
                    ldsm_x4(bh, bhb + kk * 64);
                    ldsm_x4(bl, blb + kk * 64);
                    mma16816(acc[nf], af[2 * kk],     bh);
                    mma16816(acc[nf], af[2 * kk],     bl);
                    mma16816(acc[nf], af[2 * kk + 1], bh + 2);
                    mma16816(acc[nf], af[2 * kk + 1], bl + 2);
                }
                uint32_t b2h[2], b2l[2];
                ldsm_x2(b2h, bhb + 512);
                ldsm_x2(b2l, blb + 512);
                mma16816(acc[nf], af[16], b2h);
                mma16816(acc[nf], af[16], b2l);
            }
        }
        __syncthreads();   // A ldsm reads done before es overwrite

        if (warp < 8) {
            int r0 = warp * 16;
            int rowA = r0 + (lane >> 2);
            #pragma unroll
            for (int nf = 0; nf < 13; nf++) {
                int col = nf * 8 + 2 * (lane & 3);
                es[col * 129 + rowA]           = acc[nf][0];
                es[(col + 1) * 129 + rowA]     = acc[nf][1];
                es[col * 129 + rowA + 8]       = acc[nf][2];
                es[(col + 1) * 129 + rowA + 8] = acc[nf][3];
            }
        }
        __syncthreads();

        #pragma unroll 1
        for (int er = warp; er < 128; er += 12) {
            int eg = ebase + er;
            if (eg >= ne) break;
            int s = s_src[er], d = s_dst[er];
            float ec0 = 0.f, ec1 = 0.f, ec2 = 0.f, ec3 = 0.f, d0 = 0.f, d1 = 0.f;
            float4 qv = make_float4(0,0,0,0), kv = qv, vv = qv;
            if (lane < 25) {
                ec0 = es[(4 * lq + 0) * 129 + er];
                ec1 = es[(4 * lq + 1) * 129 + er];
                ec2 = es[(4 * lq + 2) * 129 + er];
                ec3 = es[(4 * lq + 3) * 129 + er];
                qv = *(const float4*)(g_nproj + (size_t)d * 400 + lq * 4);
                kv = *(const float4*)(g_nproj + (size_t)s * 400 + 100 + lq * 4);
                vv = *(const float4*)(g_nproj + (size_t)s * 400 + 200 + lq * 4);
                d0 = qv.x * (kv.x + ec0) + qv.y * (kv.y + ec1);
                d1 = qv.z * (kv.z + ec2) + qv.w * (kv.w + ec3);
            }
            float p0 = ((lane < 13) ? d0 : 0.0f) + ((lane < 12) ? d1 : 0.0f);
            float p1 = ((lane < 13) ? 0.0f : d0) + ((lane < 12) ? 0.0f : d1);
            #pragma unroll
            for (int o = 16; o > 0; o >>= 1) {
                p0 += __shfl_xor_sync(0xffffffffu, p0, o);
                p1 += __shfl_xor_sync(0xffffffffu, p1, o);
            }
            float ex0 = __expf(p0 * SCALE);
            float ex1 = __expf(p1 * SCALE);
            if (lane == 0) red2(&g_denom[(size_t)d * 2], ex0, ex1);
            if (lane < 25) {
                float w0 = (lane < 13) ? ex0 : ex1;
                float w1 = (lane < 12) ? ex0 : ex1;
                red4(g_acc + (size_t)d * 100 + lq * 4,
                     w0 * (vv.x + ec0), w0 * (vv.y + ec1),
                     w1 * (vv.z + ec2), w1 * (vv.w + ec3));
            }
        }
    }
}

// ---------------------------------------------------------------------------
__global__ void k_final(float* __restrict__ out, int n) {
    int tot = n * 25;
    for (int i = blockIdx.x * blockDim.x + threadIdx.x; i < tot;
         i += gridDim.x * blockDim.x) {
        int nd = i / 25, q = i % 25;
        float den0 = g_denom[(size_t)nd * 2 + 0];
        float den1 = g_denom[(size_t)nd * 2 + 1];
        float dxy = (q < 13) ? den0 : den1;
        float dzw = (q < 12) ? den0 : den1;
        float rxy = (dxy > 0.0f) ? (1.0f / dxy) : 0.0f;
        float rzw = (dzw > 0.0f) ? (1.0f / dzw) : 0.0f;
        float4 a4 = ((const float4*)g_acc)[i];
        float4 sk = *(const float4*)(g_nproj + (size_t)nd * 400 + 300 + q * 4);
        float4 o;
        o.x = a4.x * rxy + sk.x;
        o.y = a4.y * rxy + sk.y;
        o.z = a4.z * rzw + sk.z;
        o.w = a4.w * rzw + sk.w;
        ((float4*)out)[i] = o;
    }
}

// ---------------------------------------------------------------------------
extern "C" void kernel_launch(void* const* d_in, const int* in_sizes, int n_in,
                              void* d_out, int out_size) {
    const float* x   = (const float*)d_in[0];
    const float* lu  = (const float*)d_in[1];
    const float* t   = (const float*)d_in[2];
    const float* msg = (const float*)d_in[3];
    const float* Wt  = (const float*)d_in[4];
    const float* bt  = (const float*)d_in[5];
    const float* Wq  = (const float*)d_in[6];
    const float* bq  = (const float*)d_in[7];
    const float* Wk  = (const float*)d_in[8];
    const float* bk  = (const float*)d_in[9];
    const float* Wv  = (const float*)d_in[10];
    const float* bv  = (const float*)d_in[11];
    const float* We  = (const float*)d_in[12];
    const float* Ws  = (const float*)d_in[13];
    const float* bs  = (const float*)d_in[14];
    const int*   ei  = (const int*)d_in[15];

    int n  = in_sizes[1];
    int ne = in_sizes[2];
    float* out = (float*)d_out;

    int dev = 0;
    cudaGetDevice(&dev);
    int nsm = 148;
    cudaDeviceGetAttribute(&nsm, cudaDevAttrMultiProcessorCount, dev);

    size_t smem1 = (size_t)(40000 + 400 + 12 * 400) * 4;
    cudaFuncSetAttribute(k_nproj, cudaFuncAttributeMaxDynamicSharedMemorySize, (int)smem1);
    cudaFuncSetAttribute(k_edge,  cudaFuncAttributeMaxDynamicSharedMemorySize, SMEM_EDGE_BYTES);

    k_zero<<<2048, 256>>>(n);
    k_nproj<<<nsm, 384, smem1>>>(x, Wq, bq, Wk, bk, Wv, bv, Ws, bs, n);
    k_edge<<<nsm, 384, SMEM_EDGE_BYTES>>>(lu, t, msg, Wt, bt, We, ei, n, ne);
    k_final<<<4096, 256>>>(out, n);
}

// round 7
// speedup vs baseline: 1.3921x; 1.0680x over previous
#include <cuda_runtime.h>
#include <cuda_fp16.h>
#include <cstdint>

#define HC 100
typedef unsigned long long ull;

__device__ float g_nproj[(size_t)100000 * 400];
__device__ float g_acc[(size_t)100000 * HC];
__device__ float g_denom[(size_t)100000 * 2];

__device__ __forceinline__ void ffma2(ull &acc, ull a, ull b) {
    asm("fma.rn.f32x2 %0, %1, %2, %0;" : "+l"(acc) : "l"(a), "l"(b));
}
__device__ __forceinline__ ull pack2(float x, float y) {
    ull r; asm("mov.b64 %0, {%1, %2};" : "=l"(r) : "f"(x), "f"(y)); return r;
}
__device__ __forceinline__ float2 unpack2(ull v) {
    float2 f; asm("mov.b64 {%0, %1}, %2;" : "=f"(f.x), "=f"(f.y) : "l"(v)); return f;
}
__device__ __forceinline__ void red2(float* p, float a, float b) {
    asm volatile("red.global.add.v2.f32 [%0], {%1, %2};" :: "l"(p), "f"(a), "f"(b) : "memory");
}
__device__ __forceinline__ void red4(float* p, float a, float b, float c, float d) {
    asm volatile("red.global.add.v4.f32 [%0], {%1, %2, %3, %4};"
                 :: "l"(p), "f"(a), "f"(b), "f"(c), "f"(d) : "memory");
}
__device__ __forceinline__ void prefetchL2(const void* p) {
    asm volatile("prefetch.global.L2 [%0];" :: "l"(p));
}
__device__ __forceinline__ uint32_t smem_u32(const void* p) {
    uint32_t a;
    asm("{ .reg .u64 t; cvta.to.shared.u64 t, %1; cvt.u32.u64 %0, t; }" : "=r"(a) : "l"(p));
    return a;
}
__device__ __forceinline__ void ldsm_x4(uint32_t* r, uint32_t a) {
    asm volatile("ldmatrix.sync.aligned.m8n8.x4.shared.b16 {%0,%1,%2,%3}, [%4];"
                 : "=r"(r[0]), "=r"(r[1]), "=r"(r[2]), "=r"(r[3]) : "r"(a));
}
__device__ __forceinline__ void ldsm_x2(uint32_t* r, uint32_t a) {
    asm volatile("ldmatrix.sync.aligned.m8n8.x2.shared.b16 {%0,%1}, [%2];"
                 : "=r"(r[0]), "=r"(r[1]) : "r"(a));
}
__device__ __forceinline__ void mma16816(float* c, const uint32_t* a, const uint32_t* b) {
    asm volatile("mma.sync.aligned.m16n8k16.row.col.f32.f16.f16.f32 "
                 "{%0,%1,%2,%3}, {%4,%5,%6,%7}, {%8,%9}, {%0,%1,%2,%3};"
                 : "+f"(c[0]), "+f"(c[1]), "+f"(c[2]), "+f"(c[3])
                 : "r"(a[0]), "r"(a[1]), "r"(a[2]), "r"(a[3]), "r"(b[0]), "r"(b[1]));
}

// ---------------------------------------------------------------------------
__global__ void k_zero(int n) {
    int na = n * 25;
    int tot = na + n;
    float4 z4 = make_float4(0.f, 0.f, 0.f, 0.f);
    for (int i = blockIdx.x * blockDim.x + threadIdx.x; i < tot;
         i += gridDim.x * blockDim.x) {
        if (i < na) ((float4*)g_acc)[i] = z4;
        else        ((float2*)g_denom)[i - na] = make_float2(0.f, 0.f);
    }
}

// ---------------------------------------------------------------------------
// Node projections (FFMA2 version, proven in R2)
// ---------------------------------------------------------------------------
__global__ void __launch_bounds__(384, 1) k_nproj(
    const float* __restrict__ x,
    const float* __restrict__ Wq, const float* __restrict__ bq,
    const float* __restrict__ Wk, const float* __restrict__ bk,
    const float* __restrict__ Wv, const float* __restrict__ bv,
    const float* __restrict__ Ws, const float* __restrict__ bs,
    int n)
{
    extern __shared__ float sm[];
    float* wsm  = sm;
    float* bsm  = sm + 40000;
    float* actb = sm + 40400;

    int tid = threadIdx.x;
    for (int i = tid; i < 40000; i += 384) {
        int k = i / 400, c = i % 400;
        float v;
        if      (c < 100) v = Wq[k * 100 + c];
        else if (c < 200) v = Wk[k * 100 + c - 100];
        else if (c < 300) v = Wv[k * 100 + c - 200];
        else              v = Ws[k * 100 + c - 300];
        wsm[i] = v;
    }
    for (int i = tid; i < 400; i += 384) {
        bsm[i] = (i < 100) ? bq[i] : (i < 200) ? bk[i - 100]
               : (i < 300) ? bv[i - 200] : bs[i - 300];
    }
    __syncthreads();

    int warp = tid >> 5, lane = tid & 31;
    int gwarp = blockIdx.x * 12 + warp;
    int nwarps = gridDim.x * 12;
    float* aw = actb + warp * 400;
    int lq = (lane < 25) ? lane : 24;

    int nblocks = (n + 3) >> 2;
    for (int blk = gwarp; blk < nblocks; blk += nwarps) {
        int nbase = blk * 4;
        __syncwarp();
        #pragma unroll
        for (int e = 0; e < 4; e++) {
            int nd = nbase + e; if (nd >= n) nd = n - 1;
            if (lane < 25)
                ((float4*)(aw + e * 100))[lane] =
                    ((const float4*)(x + (size_t)nd * 100))[lane];
        }
        __syncwarp();

        ull acc[4][4][2];
        #pragma unroll
        for (int g = 0; g < 4; g++) {
            ulonglong2 b2 = *(const ulonglong2*)(bsm + g * 100 + lq * 4);
            #pragma unroll
            for (int e = 0; e < 4; e++) { acc[e][g][0] = b2.x; acc[e][g][1] = b2.y; }
        }

        #pragma unroll 1
        for (int k = 0; k < 100; k += 2) {
            ull ad[4][2];
            #pragma unroll
            for (int e = 0; e < 4; e++) {
                float2 a2 = *(const float2*)(aw + e * 100 + k);
                ad[e][0] = pack2(a2.x, a2.x);
                ad[e][1] = pack2(a2.y, a2.y);
            }
            #pragma unroll
            for (int g = 0; g < 4; g++) {
                ulonglong2 w0 = *(const ulonglong2*)(wsm + k * 400 + g * 100 + lq * 4);
                ulonglong2 w1 = *(const ulonglong2*)(wsm + (k + 1) * 400 + g * 100 + lq * 4);
                #pragma unroll
                for (int e = 0; e < 4; e++) {
                    ffma2(acc[e][g][0], ad[e][0], w0.x);
                    ffma2(acc[e][g][1], ad[e][0], w0.y);
                    ffma2(acc[e][g][0], ad[e][1], w1.x);
                    ffma2(acc[e][g][1], ad[e][1], w1.y);
                }
            }
        }

        #pragma unroll
        for (int e = 0; e < 4; e++) {
            int nd = nbase + e;
            if (nd < n && lane < 25) {
                #pragma unroll
                for (int g = 0; g < 4; g++) {
                    float2 lo = unpack2(acc[e][g][0]);
                    float2 hi = unpack2(acc[e][g][1]);
                    *(float4*)(g_nproj + (size_t)nd * 400 + g * 100 + lq * 4) =
                        make_float4(lo.x, lo.y, hi.x, hi.y);
                }
            }
        }
        __syncwarp();
    }
}

// ---------------------------------------------------------------------------
// Edge kernel: HMMA fp16 single-pass GEMM
//   D[128 edges, 104] = A[128,272] * WT[104,272] ; A fp16, W fp16
// ---------------------------------------------------------------------------
#define SM_W   0
#define SM_A   58240
#define SM_SRC 129920
#define SM_DST 130432
#define SM_REL 130944
#define SM_WTB 131456
#define SMEM_EDGE_BYTES 132256

__device__ __forceinline__ void build_tile(
    char* smb, const float* __restrict__ msg, int ebase, int ne, int tid)
{
    const float* wtb = (const float*)(smb + SM_WTB);   // Wt | bt
    const float* rel = (const float*)(smb + SM_REL);
    for (int idx = tid; idx < 4352; idx += 384) {
        int r = idx / 34, g = idx - r * 34;
        int j0 = g * 8;
        int eg = ebase + r; if (eg >= ne) eg = ne - 1;
        float v[8];
        if (j0 + 8 <= 100) {
            float rr = rel[r];
            #pragma unroll
            for (int i = 0; i < 8; i++)
                v[i] = __cosf(fmaf(rr, wtb[j0 + i], wtb[100 + j0 + i]));
        } else if (j0 >= 104) {
            const float4* m4 = (const float4*)(msg + (size_t)eg * 172 + (j0 - 100));
            float4 a = m4[0], b = m4[1];
            v[0] = a.x; v[1] = a.y; v[2] = a.z; v[3] = a.w;
            v[4] = b.x; v[5] = b.y; v[6] = b.z; v[7] = b.w;
        } else {
            float rr = rel[r];
            const float* mrow = msg + (size_t)eg * 172;
            #pragma unroll
            for (int i = 0; i < 8; i++) {
                int j = j0 + i;
                v[i] = (j < 100) ? __cosf(fmaf(rr, wtb[j], wtb[100 + j])) : mrow[j - 100];
            }
        }
        uint32_t p[4];
        #pragma unroll
        for (int i = 0; i < 4; i++) {
            __half2 h;
            h.x = __float2half_rn(v[2 * i]);
            h.y = __float2half_rn(v[2 * i + 1]);
            p[i] = *reinterpret_cast<uint32_t*>(&h);
        }
        *(uint4*)(smb + SM_A + r * 560 + j0 * 2) = make_uint4(p[0], p[1], p[2], p[3]);
    }
}

__global__ void __launch_bounds__(384, 1) k_edge(
    const float* __restrict__ lu, const float* __restrict__ t,
    const float* __restrict__ msg,
    const float* __restrict__ Wt, const float* __restrict__ bt,
    const float* __restrict__ We, const int* __restrict__ ei,
    int n, int ne)
{
    extern __shared__ char smb[];
    uint32_t sbase = smem_u32(smb);
    int tid = threadIdx.x;
    int warp = tid >> 5, lane = tid & 31;

    // one-time: W [104 n-rows][272 k] fp16, stride 280; cols>=100 zero
    for (int idx = tid; idx < 104 * 272; idx += 384) {
        int c = idx / 272, j = idx - c * 272;
        float w = (c < 100) ? We[j * 100 + c] : 0.0f;
        *(__half*)(smb + SM_W + c * 560 + j * 2) = __float2half_rn(w);
    }
    {
        float* wtb = (float*)(smb + SM_WTB);
        for (int i = tid; i < 100; i += 384) { wtb[i] = Wt[i]; wtb[100 + i] = bt[i]; }
    }
    __syncthreads();

    int* s_src = (int*)(smb + SM_SRC);
    int* s_dst = (int*)(smb + SM_DST);
    float* s_rel = (float*)(smb + SM_REL);
    float* es = (float*)(smb + SM_A);   // es[104][129] overlays A after MMA
    const float SCALE = 0.14142135623730951f;
    int lq = (lane < 25) ? lane : 24;

    int ntiles = (ne + 127) >> 7;
    for (int tile = blockIdx.x; tile < ntiles; tile += gridDim.x) {
        int ebase = tile << 7;
        __syncthreads();   // prev epilogue done before overwriting es/A/meta

        if (tid < 128) {
            int eg = ebase + tid;
            bool valid = eg < ne;
            int eidx = valid ? eg : 0;
            int s = ei[eidx], d = ei[ne + eidx];
            s_src[tid] = s; s_dst[tid] = d;
            s_rel[tid] = valid ? (lu[s] - t[eidx]) : 0.0f;
            if (valid) {
                const char* qb = (const char*)(g_nproj + (size_t)d * 400);
                const char* kb = (const char*)(g_nproj + (size_t)s * 400 + 100);
                const char* vb = (const char*)(g_nproj + (size_t)s * 400 + 200);
                #pragma unroll
                for (int o = 0; o < 400; o += 128) {
                    prefetchL2(qb + o); prefetchL2(kb + o); prefetchL2(vb + o);
                }
            }
        }
        __syncthreads();

        build_tile(smb, msg, ebase, ne, tid);   // A fp16
        __syncthreads();

        float acc[13][4];
        #pragma unroll
        for (int nf = 0; nf < 13; nf++) {
            acc[nf][0] = 0.f; acc[nf][1] = 0.f; acc[nf][2] = 0.f; acc[nf][3] = 0.f;
        }

        if (warp < 8) {
            int r0 = warp * 16;
            uint32_t abase = sbase + SM_A
                           + (uint32_t)((r0 + (lane & 15)) * 560 + (lane >> 4) * 16);
            uint32_t af[17][4];
            #pragma unroll
            for (int k = 0; k < 17; k++) ldsm_x4(af[k], abase + k * 32);

            #pragma unroll
            for (int nf = 0; nf < 13; nf++) {
                uint32_t bb = sbase + SM_W
                    + (uint32_t)((nf * 8 + (lane & 7)) * 560 + (lane >> 3) * 16);
                #pragma unroll
                for (int kk = 0; kk < 8; kk++) {
                    uint32_t bh[4];
                    ldsm_x4(bh, bb + kk * 64);
                    mma16816(acc[nf], af[2 * kk],     bh);
                    mma16816(acc[nf], af[2 * kk + 1], bh + 2);
                }
                uint32_t b2[2];
                ldsm_x2(b2, bb + 512);
                mma16816(acc[nf], af[16], b2);
            }
        }
        __syncthreads();   // A ldsm reads done before es overwrite

        if (warp < 8) {
            int r0 = warp * 16;
            int rowA = r0 + (lane >> 2);
            #pragma unroll
            for (int nf = 0; nf < 13; nf++) {
                int col = nf * 8 + 2 * (lane & 3);
                es[col * 129 + rowA]           = acc[nf][0];
                es[(col + 1) * 129 + rowA]     = acc[nf][1];
                es[col * 129 + rowA + 8]       = acc[nf][2];
                es[(col + 1) * 129 + rowA + 8] = acc[nf][3];
            }
        }
        __syncthreads();

        #pragma unroll 1
        for (int er = warp; er < 128; er += 12) {
            int eg = ebase + er;
            if (eg >= ne) break;
            int s = s_src[er], d = s_dst[er];
            float ec0 = 0.f, ec1 = 0.f, ec2 = 0.f, ec3 = 0.f, d0 = 0.f, d1 = 0.f;
            float4 qv = make_float4(0,0,0,0), kv = qv, vv = qv;
            if (lane < 25) {
                ec0 = es[(4 * lq + 0) * 129 + er];
                ec1 = es[(4 * lq + 1) * 129 + er];
                ec2 = es[(4 * lq + 2) * 129 + er];
                ec3 = es[(4 * lq + 3) * 129 + er];
                qv = *(const float4*)(g_nproj + (size_t)d * 400 + lq * 4);
                kv = *(const float4*)(g_nproj + (size_t)s * 400 + 100 + lq * 4);
                vv = *(const float4*)(g_nproj + (size_t)s * 400 + 200 + lq * 4);
                d0 = qv.x * (kv.x + ec0) + qv.y * (kv.y + ec1);
                d1 = qv.z * (kv.z + ec2) + qv.w * (kv.w + ec3);
            }
            float p0 = ((lane < 13) ? d0 : 0.0f) + ((lane < 12) ? d1 : 0.0f);
            float p1 = ((lane < 13) ? 0.0f : d0) + ((lane < 12) ? 0.0f : d1);
            #pragma unroll
            for (int o = 16; o > 0; o >>= 1) {
                p0 += __shfl_xor_sync(0xffffffffu, p0, o);
                p1 += __shfl_xor_sync(0xffffffffu, p1, o);
            }
            float ex0 = __expf(p0 * SCALE);
            float ex1 = __expf(p1 * SCALE);
            if (lane == 0) red2(&g_denom[(size_t)d * 2], ex0, ex1);
            if (lane < 25) {
                float w0 = (lane < 13) ? ex0 : ex1;
                float w1 = (lane < 12) ? ex0 : ex1;
                red4(g_acc + (size_t)d * 100 + lq * 4,
                     w0 * (vv.x + ec0), w0 * (vv.y + ec1),
                     w1 * (vv.z + ec2), w1 * (vv.w + ec3));
            }
        }
    }
}

// ---------------------------------------------------------------------------
__global__ void k_final(float* __restrict__ out, int n) {
    int tot = n * 25;
    for (int i = blockIdx.x * blockDim.x + threadIdx.x; i < tot;
         i += gridDim.x * blockDim.x) {
        int nd = i / 25, q = i % 25;
        float den0 = g_denom[(size_t)nd * 2 + 0];
        float den1 = g_denom[(size_t)nd * 2 + 1];
        float dxy = (q < 13) ? den0 : den1;
        float dzw = (q < 12) ? den0 : den1;
        float rxy = (dxy > 0.0f) ? (1.0f / dxy) : 0.0f;
        float rzw = (dzw > 0.0f) ? (1.0f / dzw) : 0.0f;
        float4 a4 = ((const float4*)g_acc)[i];
        float4 sk = *(const float4*)(g_nproj + (size_t)nd * 400 + 300 + q * 4);
        float4 o;
        o.x = a4.x * rxy + sk.x;
        o.y = a4.y * rxy + sk.y;
        o.z = a4.z * rzw + sk.z;
        o.w = a4.w * rzw + sk.w;
        ((float4*)out)[i] = o;
    }
}

// ---------------------------------------------------------------------------
extern "C" void kernel_launch(void* const* d_in, const int* in_sizes, int n_in,
                              void* d_out, int out_size) {
    const float* x   = (const float*)d_in[0];
    const float* lu  = (const float*)d_in[1];
    const float* t   = (const float*)d_in[2];
    const float* msg = (const float*)d_in[3];
    const float* Wt  = (const float*)d_in[4];
    const float* bt  = (const float*)d_in[5];
    const float* Wq  = (const float*)d_in[6];
    const float* bq  = (const float*)d_in[7];
    const float* Wk  = (const float*)d_in[8];
    const float* bk  = (const float*)d_in[9];
    const float* Wv  = (const float*)d_in[10];
    const float* bv  = (const float*)d_in[11];
    const float* We  = (const float*)d_in[12];
    const float* Ws  = (const float*)d_in[13];
    const float* bs  = (const float*)d_in[14];
    const int*   ei  = (const int*)d_in[15];

    int n  = in_sizes[1];
    int ne = in_sizes[2];
    float* out = (float*)d_out;

    int dev = 0;
    cudaGetDevice(&dev);
    int nsm = 148;
    cudaDeviceGetAttribute(&nsm, cudaDevAttrMultiProcessorCount, dev);

    size_t smem1 = (size_t)(40000 + 400 + 12 * 400) * 4;
    cudaFuncSetAttribute(k_nproj, cudaFuncAttributeMaxDynamicSharedMemorySize, (int)smem1);
    cudaFuncSetAttribute(k_edge,  cudaFuncAttributeMaxDynamicSharedMemorySize, SMEM_EDGE_BYTES);

    k_zero<<<2048, 256>>>(n);
    k_nproj<<<nsm, 384, smem1>>>(x, Wq, bq, Wk, bk, Wv, bv, Ws, bs, n);
    k_edge<<<nsm, 384, SMEM_EDGE_BYTES>>>(lu, t, msg, Wt, bt, We, ei, n, ne);
    k_final<<<4096, 256>>>(out, n);
}

// round 8
// speedup vs baseline: 1.5219x; 1.0932x over previous
#include <cuda_runtime.h>
#include <cuda_fp16.h>
#include <cstdint>

#define HC 100
typedef unsigned long long ull;

__device__ float g_nproj[(size_t)100000 * 400];
__device__ float g_acc[(size_t)100000 * HC];
__device__ float g_denom[(size_t)100000 * 2];

__device__ __forceinline__ void ffma2(ull &acc, ull a, ull b) {
    asm("fma.rn.f32x2 %0, %1, %2, %0;" : "+l"(acc) : "l"(a), "l"(b));
}
__device__ __forceinline__ ull pack2(float x, float y) {
    ull r; asm("mov.b64 %0, {%1, %2};" : "=l"(r) : "f"(x), "f"(y)); return r;
}
__device__ __forceinline__ float2 unpack2(ull v) {
    float2 f; asm("mov.b64 {%0, %1}, %2;" : "=f"(f.x), "=f"(f.y) : "l"(v)); return f;
}
__device__ __forceinline__ void red2(float* p, float a, float b) {
    asm volatile("red.global.add.v2.f32 [%0], {%1, %2};" :: "l"(p), "f"(a), "f"(b) : "memory");
}
__device__ __forceinline__ void red4(float* p, float a, float b, float c, float d) {
    asm volatile("red.global.add.v4.f32 [%0], {%1, %2, %3, %4};"
                 :: "l"(p), "f"(a), "f"(b), "f"(c), "f"(d) : "memory");
}
__device__ __forceinline__ void prefetchL2(const void* p) {
    asm volatile("prefetch.global.L2 [%0];" :: "l"(p));
}
__device__ __forceinline__ uint32_t smem_u32(const void* p) {
    uint32_t a;
    asm("{ .reg .u64 t; cvta.to.shared.u64 t, %1; cvt.u32.u64 %0, t; }" : "=r"(a) : "l"(p));
    return a;
}
__device__ __forceinline__ void ldsm_x4(uint32_t* r, uint32_t a) {
    asm volatile("ldmatrix.sync.aligned.m8n8.x4.shared.b16 {%0,%1,%2,%3}, [%4];"
                 : "=r"(r[0]), "=r"(r[1]), "=r"(r[2]), "=r"(r[3]) : "r"(a));
}
__device__ __forceinline__ void ldsm_x2(uint32_t* r, uint32_t a) {
    asm volatile("ldmatrix.sync.aligned.m8n8.x2.shared.b16 {%0,%1}, [%2];"
                 : "=r"(r[0]), "=r"(r[1]) : "r"(a));
}
__device__ __forceinline__ void mma16816(float* c, const uint32_t* a, const uint32_t* b) {
    asm volatile("mma.sync.aligned.m16n8k16.row.col.f32.f16.f16.f32 "
                 "{%0,%1,%2,%3}, {%4,%5,%6,%7}, {%8,%9}, {%0,%1,%2,%3};"
                 : "+f"(c[0]), "+f"(c[1]), "+f"(c[2]), "+f"(c[3])
                 : "r"(a[0]), "r"(a[1]), "r"(a[2]), "r"(a[3]), "r"(b[0]), "r"(b[1]));
}

// ---------------------------------------------------------------------------
__global__ void k_zero(int n) {
    int na = n * 25;
    int tot = na + n;
    float4 z4 = make_float4(0.f, 0.f, 0.f, 0.f);
    for (int i = blockIdx.x * blockDim.x + threadIdx.x; i < tot;
         i += gridDim.x * blockDim.x) {
        if (i < na) ((float4*)g_acc)[i] = z4;
        else        ((float2*)g_denom)[i - na] = make_float2(0.f, 0.f);
    }
}

// ---------------------------------------------------------------------------
// Node projections (FFMA2 version, proven in R2)
// ---------------------------------------------------------------------------
__global__ void __launch_bounds__(384, 1) k_nproj(
    const float* __restrict__ x,
    const float* __restrict__ Wq, const float* __restrict__ bq,
    const float* __restrict__ Wk, const float* __restrict__ bk,
    const float* __restrict__ Wv, const float* __restrict__ bv,
    const float* __restrict__ Ws, const float* __restrict__ bs,
    int n)
{
    extern __shared__ float sm[];
    float* wsm  = sm;
    float* bsm  = sm + 40000;
    float* actb = sm + 40400;

    int tid = threadIdx.x;
    for (int i = tid; i < 40000; i += 384) {
        int k = i / 400, c = i % 400;
        float v;
        if      (c < 100) v = Wq[k * 100 + c];
        else if (c < 200) v = Wk[k * 100 + c - 100];
        else if (c < 300) v = Wv[k * 100 + c - 200];
        else              v = Ws[k * 100 + c - 300];
        wsm[i] = v;
    }
    for (int i = tid; i < 400; i += 384) {
        bsm[i] = (i < 100) ? bq[i] : (i < 200) ? bk[i - 100]
               : (i < 300) ? bv[i - 200] : bs[i - 300];
    }
    __syncthreads();

    int warp = tid >> 5, lane = tid & 31;
    int gwarp = blockIdx.x * 12 + warp;
    int nwarps = gridDim.x * 12;
    float* aw = actb + warp * 400;
    int lq = (lane < 25) ? lane : 24;

    int nblocks = (n + 3) >> 2;
    for (int blk = gwarp; blk < nblocks; blk += nwarps) {
        int nbase = blk * 4;
        __syncwarp();
        #pragma unroll
        for (int e = 0; e < 4; e++) {
            int nd = nbase + e; if (nd >= n) nd = n - 1;
            if (lane < 25)
                ((float4*)(aw + e * 100))[lane] =
                    ((const float4*)(x + (size_t)nd * 100))[lane];
        }
        __syncwarp();

        ull acc[4][4][2];
        #pragma unroll
        for (int g = 0; g < 4; g++) {
            ulonglong2 b2 = *(const ulonglong2*)(bsm + g * 100 + lq * 4);
            #pragma unroll
            for (int e = 0; e < 4; e++) { acc[e][g][0] = b2.x; acc[e][g][1] = b2.y; }
        }

        #pragma unroll 1
        for (int k = 0; k < 100; k += 2) {
            ull ad[4][2];
            #pragma unroll
            for (int e = 0; e < 4; e++) {
                float2 a2 = *(const float2*)(aw + e * 100 + k);
                ad[e][0] = pack2(a2.x, a2.x);
                ad[e][1] = pack2(a2.y, a2.y);
            }
            #pragma unroll
            for (int g = 0; g < 4; g++) {
                ulonglong2 w0 = *(const ulonglong2*)(wsm + k * 400 + g * 100 + lq * 4);
                ulonglong2 w1 = *(const ulonglong2*)(wsm + (k + 1) * 400 + g * 100 + lq * 4);
                #pragma unroll
                for (int e = 0; e < 4; e++) {
                    ffma2(acc[e][g][0], ad[e][0], w0.x);
                    ffma2(acc[e][g][1], ad[e][0], w0.y);
                    ffma2(acc[e][g][0], ad[e][1], w1.x);
                    ffma2(acc[e][g][1], ad[e][1], w1.y);
                }
            }
        }

        #pragma unroll
        for (int e = 0; e < 4; e++) {
            int nd = nbase + e;
            if (nd < n && lane < 25) {
                #pragma unroll
                for (int g = 0; g < 4; g++) {
                    float2 lo = unpack2(acc[e][g][0]);
                    float2 hi = unpack2(acc[e][g][1]);
                    *(float4*)(g_nproj + (size_t)nd * 400 + g * 100 + lq * 4) =
                        make_float4(lo.x, lo.y, hi.x, hi.y);
                }
            }
        }
        __syncwarp();
    }
}

// ---------------------------------------------------------------------------
// Edge kernel: HMMA fp16 single-pass GEMM, 64-edge tiles, 2 CTAs/SM overlap
//   D[64 edges, 104] = A[64,272] * WT[104,272]
// ---------------------------------------------------------------------------
#define SM_W   0
#define SM_A   58240
#define SM_SRC 94080
#define SM_DST 94336
#define SM_REL 94592
#define SM_WTB 94848
#define SMEM_EDGE_BYTES 95648
#define ETILE 64

__device__ __forceinline__ void build_tile(
    char* smb, const float* __restrict__ msg, int ebase, int ne, int tid)
{
    const float* wtb = (const float*)(smb + SM_WTB);   // Wt | bt
    const float* rel = (const float*)(smb + SM_REL);
    for (int idx = tid; idx < ETILE * 34; idx += 256) {
        int r = idx / 34, g = idx - r * 34;
        int j0 = g * 8;
        int eg = ebase + r; if (eg >= ne) eg = ne - 1;
        float v[8];
        if (j0 + 8 <= 100) {
            float rr = rel[r];
            #pragma unroll
            for (int i = 0; i < 8; i++)
                v[i] = __cosf(fmaf(rr, wtb[j0 + i], wtb[100 + j0 + i]));
        } else if (j0 >= 104) {
            const float4* m4 = (const float4*)(msg + (size_t)eg * 172 + (j0 - 100));
            float4 a = m4[0], b = m4[1];
            v[0] = a.x; v[1] = a.y; v[2] = a.z; v[3] = a.w;
            v[4] = b.x; v[5] = b.y; v[6] = b.z; v[7] = b.w;
        } else {
            float rr = rel[r];
            const float* mrow = msg + (size_t)eg * 172;
            #pragma unroll
            for (int i = 0; i < 8; i++) {
                int j = j0 + i;
                v[i] = (j < 100) ? __cosf(fmaf(rr, wtb[j], wtb[100 + j])) : mrow[j - 100];
            }
        }
        uint32_t p[4];
        #pragma unroll
        for (int i = 0; i < 4; i++) {
            __half2 h;
            h.x = __float2half_rn(v[2 * i]);
            h.y = __float2half_rn(v[2 * i + 1]);
            p[i] = *reinterpret_cast<uint32_t*>(&h);
        }
        *(uint4*)(smb + SM_A + r * 560 + j0 * 2) = make_uint4(p[0], p[1], p[2], p[3]);
    }
}

__global__ void __launch_bounds__(256, 2) k_edge(
    const float* __restrict__ lu, const float* __restrict__ t,
    const float* __restrict__ msg,
    const float* __restrict__ Wt, const float* __restrict__ bt,
    const float* __restrict__ We, const int* __restrict__ ei,
    int n, int ne)
{
    extern __shared__ char smb[];
    uint32_t sbase = smem_u32(smb);
    int tid = threadIdx.x;
    int warp = tid >> 5, lane = tid & 31;

    // one-time: W [104 n-rows][272 k] fp16, stride 280; cols>=100 zero
    for (int idx = tid; idx < 104 * 272; idx += 256) {
        int c = idx / 272, j = idx - c * 272;
        float w = (c < 100) ? We[j * 100 + c] : 0.0f;
        *(__half*)(smb + SM_W + c * 560 + j * 2) = __float2half_rn(w);
    }
    {
        float* wtb = (float*)(smb + SM_WTB);
        for (int i = tid; i < 100; i += 256) { wtb[i] = Wt[i]; wtb[100 + i] = bt[i]; }
    }
    __syncthreads();

    int* s_src = (int*)(smb + SM_SRC);
    int* s_dst = (int*)(smb + SM_DST);
    float* s_rel = (float*)(smb + SM_REL);
    float* es = (float*)(smb + SM_A);   // es[104][65] overlays A after MMA
    const float SCALE = 0.14142135623730951f;
    int lq = (lane < 25) ? lane : 24;

    // MMA role: warp w -> M-block (w&3)*16, N-half (w>>2)
    int mrow = (warp & 3) * 16;
    int nf0  = (warp >> 2) * 7;
    int nfe  = (warp >> 2) ? 13 : 7;

    int ntiles = (ne + ETILE - 1) / ETILE;
    for (int tile = blockIdx.x; tile < ntiles; tile += gridDim.x) {
        int ebase = tile * ETILE;
        __syncthreads();   // prev epilogue done before overwriting es/A/meta

        if (tid < ETILE) {
            int eg = ebase + tid;
            bool valid = eg < ne;
            int eidx = valid ? eg : 0;
            int s = ei[eidx], d = ei[ne + eidx];
            s_src[tid] = s; s_dst[tid] = d;
            s_rel[tid] = valid ? (lu[s] - t[eidx]) : 0.0f;
            if (valid) {
                const char* qb = (const char*)(g_nproj + (size_t)d * 400);
                const char* kb = (const char*)(g_nproj + (size_t)s * 400 + 100);
                const char* vb = (const char*)(g_nproj + (size_t)s * 400 + 200);
                #pragma unroll
                for (int o = 0; o < 400; o += 128) {
                    prefetchL2(qb + o); prefetchL2(kb + o); prefetchL2(vb + o);
                }
            }
        }
        __syncthreads();

        build_tile(smb, msg, ebase, ne, tid);   // A fp16
        __syncthreads();

        float acc[7][4];
        #pragma unroll
        for (int nf = 0; nf < 7; nf++) {
            acc[nf][0] = 0.f; acc[nf][1] = 0.f; acc[nf][2] = 0.f; acc[nf][3] = 0.f;
        }

        {
            uint32_t abase = sbase + SM_A
                           + (uint32_t)((mrow + (lane & 15)) * 560 + (lane >> 4) * 16);
            uint32_t af[17][4];
            #pragma unroll
            for (int k = 0; k < 17; k++) ldsm_x4(af[k], abase + k * 32);

            #pragma unroll 1
            for (int nf = nf0; nf < nfe; nf++) {
                float* ac = acc[nf - nf0];
                uint32_t bb = sbase + SM_W
                    + (uint32_t)((nf * 8 + (lane & 7)) * 560 + (lane >> 3) * 16);
                #pragma unroll
                for (int kk = 0; kk < 8; kk++) {
                    uint32_t bh[4];
                    ldsm_x4(bh, bb + kk * 64);
                    mma16816(ac, af[2 * kk],     bh);
                    mma16816(ac, af[2 * kk + 1], bh + 2);
                }
                uint32_t b2[2];
                ldsm_x2(b2, bb + 512);
                mma16816(ac, af[16], b2);
            }
        }
        __syncthreads();   // A ldsm reads done before es overwrite

        {
            int rowA = mrow + (lane >> 2);
            #pragma unroll 1
            for (int nf = nf0; nf < nfe; nf++) {
                float* ac = acc[nf - nf0];
                int col = nf * 8 + 2 * (lane & 3);
                es[col * 65 + rowA]           = ac[0];
                es[(col + 1) * 65 + rowA]     = ac[1];
                es[col * 65 + rowA + 8]       = ac[2];
                es[(col + 1) * 65 + rowA + 8] = ac[3];
            }
        }
        __syncthreads();

        #pragma unroll 1
        for (int er = warp; er < ETILE; er += 8) {
            int eg = ebase + er;
            if (eg >= ne) break;
            int s = s_src[er], d = s_dst[er];
            float ec0 = 0.f, ec1 = 0.f, ec2 = 0.f, ec3 = 0.f, d0 = 0.f, d1 = 0.f;
            float4 qv = make_float4(0,0,0,0), kv = qv, vv = qv;
            if (lane < 25) {
                ec0 = es[(4 * lq + 0) * 65 + er];
                ec1 = es[(4 * lq + 1) * 65 + er];
                ec2 = es[(4 * lq + 2) * 65 + er];
                ec3 = es[(4 * lq + 3) * 65 + er];
                qv = *(const float4*)(g_nproj + (size_t)d * 400 + lq * 4);
                kv = *(const float4*)(g_nproj + (size_t)s * 400 + 100 + lq * 4);
                vv = *(const float4*)(g_nproj + (size_t)s * 400 + 200 + lq * 4);
                d0 = qv.x * (kv.x + ec0) + qv.y * (kv.y + ec1);
                d1 = qv.z * (kv.z + ec2) + qv.w * (kv.w + ec3);
            }
            float p0 = ((lane < 13) ? d0 : 0.0f) + ((lane < 12) ? d1 : 0.0f);
            float p1 = ((lane < 13) ? 0.0f : d0) + ((lane < 12) ? 0.0f : d1);
            #pragma unroll
            for (int o = 16; o > 0; o >>= 1) {
                p0 += __shfl_xor_sync(0xffffffffu, p0, o);
                p1 += __shfl_xor_sync(0xffffffffu, p1, o);
            }
            float ex0 = __expf(p0 * SCALE);
            float ex1 = __expf(p1 * SCALE);
            if (lane == 0) red2(&g_denom[(size_t)d * 2], ex0, ex1);
            if (lane < 25) {
                float w0 = (lane < 13) ? ex0 : ex1;
                float w1 = (lane < 12) ? ex0 : ex1;
                red4(g_acc + (size_t)d * 100 + lq * 4,
                     w0 * (vv.x + ec0), w0 * (vv.y + ec1),
                     w1 * (vv.z + ec2), w1 * (vv.w + ec3));
            }
        }
    }
}

// ---------------------------------------------------------------------------
__global__ void k_final(float* __restrict__ out, int n) {
    int tot = n * 25;
    for (int i = blockIdx.x * blockDim.x + threadIdx.x; i < tot;
         i += gridDim.x * blockDim.x) {
        int nd = i / 25, q = i % 25;
        float den0 = g_denom[(size_t)nd * 2 + 0];
        float den1 = g_denom[(size_t)nd * 2 + 1];
        float dxy = (q < 13) ? den0 : den1;
        float dzw = (q < 12) ? den0 : den1;
        float rxy = (dxy > 0.0f) ? (1.0f / dxy) : 0.0f;
        float rzw = (dzw > 0.0f) ? (1.0f / dzw) : 0.0f;
        float4 a4 = ((const float4*)g_acc)[i];
        float4 sk = *(const float4*)(g_nproj + (size_t)nd * 400 + 300 + q * 4);
        float4 o;
        o.x = a4.x * rxy + sk.x;
        o.y = a4.y * rxy + sk.y;
        o.z = a4.z * rzw + sk.z;
        o.w = a4.w * rzw + sk.w;
        ((float4*)out)[i] = o;
    }
}

// ---------------------------------------------------------------------------
extern "C" void kernel_launch(void* const* d_in, const int* in_sizes, int n_in,
                              void* d_out, int out_size) {
    const float* x   = (const float*)d_in[0];
    const float* lu  = (const float*)d_in[1];
    const float* t   = (const float*)d_in[2];
    const float* msg = (const float*)d_in[3];
    const float* Wt  = (const float*)d_in[4];
    const float* bt  = (const float*)d_in[5];
    const float* Wq  = (const float*)d_in[6];
    const float* bq  = (const float*)d_in[7];
    const float* Wk  = (const float*)d_in[8];
    const float* bk  = (const float*)d_in[9];
    const float* Wv  = (const float*)d_in[10];
    const float* bv  = (const float*)d_in[11];
    const float* We  = (const float*)d_in[12];
    const float* Ws  = (const float*)d_in[13];
    const float* bs  = (const float*)d_in[14];
    const int*   ei  = (const int*)d_in[15];

    int n  = in_sizes[1];
    int ne = in_sizes[2];
    float* out = (float*)d_out;

    int dev = 0;
    cudaGetDevice(&dev);
    int nsm = 148;
    cudaDeviceGetAttribute(&nsm, cudaDevAttrMultiProcessorCount, dev);

    size_t smem1 = (size_t)(40000 + 400 + 12 * 400) * 4;
    cudaFuncSetAttribute(k_nproj, cudaFuncAttributeMaxDynamicSharedMemorySize, (int)smem1);
    cudaFuncSetAttribute(k_edge,  cudaFuncAttributeMaxDynamicSharedMemorySize, SMEM_EDGE_BYTES);

    k_zero<<<2048, 256>>>(n);
    k_nproj<<<nsm, 384, smem1>>>(x, Wq, bq, Wk, bk, Wv, bv, Ws, bs, n);
    k_edge<<<nsm * 2, 256, SMEM_EDGE_BYTES>>>(lu, t, msg, Wt, bt, We, ei, n, ne);
    k_final<<<4096, 256>>>(out, n);
}

// round 9
// speedup vs baseline: 1.6387x; 1.0768x over previous
#include <cuda_runtime.h>
#include <cuda_fp16.h>
#include <cstdint>

#define HC 100
typedef unsigned long long ull;

__device__ float g_nproj[(size_t)100000 * 400];
__device__ float g_acc[(size_t)100000 * HC];
__device__ float g_denom[(size_t)100000 * 2];

__device__ __forceinline__ void ffma2(ull &acc, ull a, ull b) {
    asm("fma.rn.f32x2 %0, %1, %2, %0;" : "+l"(acc) : "l"(a), "l"(b));
}
__device__ __forceinline__ ull pack2(float x, float y) {
    ull r; asm("mov.b64 %0, {%1, %2};" : "=l"(r) : "f"(x), "f"(y)); return r;
}
__device__ __forceinline__ float2 unpack2(ull v) {
    float2 f; asm("mov.b64 {%0, %1}, %2;" : "=f"(f.x), "=f"(f.y) : "l"(v)); return f;
}
__device__ __forceinline__ void red2(float* p, float a, float b) {
    asm volatile("red.global.add.v2.f32 [%0], {%1, %2};" :: "l"(p), "f"(a), "f"(b) : "memory");
}
__device__ __forceinline__ void red4(float* p, float a, float b, float c, float d) {
    asm volatile("red.global.add.v4.f32 [%0], {%1, %2, %3, %4};"
                 :: "l"(p), "f"(a), "f"(b), "f"(c), "f"(d) : "memory");
}
__device__ __forceinline__ void prefetchL2(const void* p) {
    asm volatile("prefetch.global.L2 [%0];" :: "l"(p));
}
__device__ __forceinline__ uint32_t smem_u32(const void* p) {
    uint32_t a;
    asm("{ .reg .u64 t; cvta.to.shared.u64 t, %1; cvt.u32.u64 %0, t; }" : "=r"(a) : "l"(p));
    return a;
}
__device__ __forceinline__ void ldsm_x4(uint32_t* r, uint32_t a) {
    asm volatile("ldmatrix.sync.aligned.m8n8.x4.shared.b16 {%0,%1,%2,%3}, [%4];"
                 : "=r"(r[0]), "=r"(r[1]), "=r"(r[2]), "=r"(r[3]) : "r"(a));
}
__device__ __forceinline__ void ldsm_x2(uint32_t* r, uint32_t a) {
    asm volatile("ldmatrix.sync.aligned.m8n8.x2.shared.b16 {%0,%1}, [%2];"
                 : "=r"(r[0]), "=r"(r[1]) : "r"(a));
}
__device__ __forceinline__ void mma16816(float* c, const uint32_t* a, const uint32_t* b) {
    asm volatile("mma.sync.aligned.m16n8k16.row.col.f32.f16.f16.f32 "
                 "{%0,%1,%2,%3}, {%4,%5,%6,%7}, {%8,%9}, {%0,%1,%2,%3};"
                 : "+f"(c[0]), "+f"(c[1]), "+f"(c[2]), "+f"(c[3])
                 : "r"(a[0]), "r"(a[1]), "r"(a[2]), "r"(a[3]), "r"(b[0]), "r"(b[1]));
}

// ---------------------------------------------------------------------------
__global__ void k_zero(int n) {
    int na = n * 25;
    int tot = na + n;
    float4 z4 = make_float4(0.f, 0.f, 0.f, 0.f);
    for (int i = blockIdx.x * blockDim.x + threadIdx.x; i < tot;
         i += gridDim.x * blockDim.x) {
        if (i < na) ((float4*)g_acc)[i] = z4;
        else        ((float2*)g_denom)[i - na] = make_float2(0.f, 0.f);
    }
}

// ---------------------------------------------------------------------------
// Node projections (FFMA2 version, proven in R2)
// ---------------------------------------------------------------------------
__global__ void __launch_bounds__(384, 1) k_nproj(
    const float* __restrict__ x,
    const float* __restrict__ Wq, const float* __restrict__ bq,
    const float* __restrict__ Wk, const float* __restrict__ bk,
    const float* __restrict__ Wv, const float* __restrict__ bv,
    const float* __restrict__ Ws, const float* __restrict__ bs,
    int n)
{
    extern __shared__ float sm[];
    float* wsm  = sm;
    float* bsm  = sm + 40000;
    float* actb = sm + 40400;

    int tid = threadIdx.x;
    for (int i = tid; i < 40000; i += 384) {
        int k = i / 400, c = i % 400;
        float v;
        if      (c < 100) v = Wq[k * 100 + c];
        else if (c < 200) v = Wk[k * 100 + c - 100];
        else if (c < 300) v = Wv[k * 100 + c - 200];
        else              v = Ws[k * 100 + c - 300];
        wsm[i] = v;
    }
    for (int i = tid; i < 400; i += 384) {
        bsm[i] = (i < 100) ? bq[i] : (i < 200) ? bk[i - 100]
               : (i < 300) ? bv[i - 200] : bs[i - 300];
    }
    __syncthreads();

    int warp = tid >> 5, lane = tid & 31;
    int gwarp = blockIdx.x * 12 + warp;
    int nwarps = gridDim.x * 12;
    float* aw = actb + warp * 400;
    int lq = (lane < 25) ? lane : 24;

    int nblocks = (n + 3) >> 2;
    for (int blk = gwarp; blk < nblocks; blk += nwarps) {
        int nbase = blk * 4;
        __syncwarp();
        #pragma unroll
        for (int e = 0; e < 4; e++) {
            int nd = nbase + e; if (nd >= n) nd = n - 1;
            if (lane < 25)
                ((float4*)(aw + e * 100))[lane] =
                    ((const float4*)(x + (size_t)nd * 100))[lane];
        }
        __syncwarp();

        ull acc[4][4][2];
        #pragma unroll
        for (int g = 0; g < 4; g++) {
            ulonglong2 b2 = *(const ulonglong2*)(bsm + g * 100 + lq * 4);
            #pragma unroll
            for (int e = 0; e < 4; e++) { acc[e][g][0] = b2.x; acc[e][g][1] = b2.y; }
        }

        #pragma unroll 1
        for (int k = 0; k < 100; k += 2) {
            ull ad[4][2];
            #pragma unroll
            for (int e = 0; e < 4; e++) {
                float2 a2 = *(const float2*)(aw + e * 100 + k);
                ad[e][0] = pack2(a2.x, a2.x);
                ad[e][1] = pack2(a2.y, a2.y);
            }
            #pragma unroll
            for (int g = 0; g < 4; g++) {
                ulonglong2 w0 = *(const ulonglong2*)(wsm + k * 400 + g * 100 + lq * 4);
                ulonglong2 w1 = *(const ulonglong2*)(wsm + (k + 1) * 400 + g * 100 + lq * 4);
                #pragma unroll
                for (int e = 0; e < 4; e++) {
                    ffma2(acc[e][g][0], ad[e][0], w0.x);
                    ffma2(acc[e][g][1], ad[e][0], w0.y);
                    ffma2(acc[e][g][0], ad[e][1], w1.x);
                    ffma2(acc[e][g][1], ad[e][1], w1.y);
                }
            }
        }

        #pragma unroll
        for (int e = 0; e < 4; e++) {
            int nd = nbase + e;
            if (nd < n && lane < 25) {
                #pragma unroll
                for (int g = 0; g < 4; g++) {
                    float2 lo = unpack2(acc[e][g][0]);
                    float2 hi = unpack2(acc[e][g][1]);
                    *(float4*)(g_nproj + (size_t)nd * 400 + g * 100 + lq * 4) =
                        make_float4(lo.x, lo.y, hi.x, hi.y);
                }
            }
        }
        __syncwarp();
    }
}

// ---------------------------------------------------------------------------
// Edge kernel: HMMA fp16 single-pass GEMM, 64-edge tiles, 2 CTAs/SM,
// row-major es + pair-interleaved epilogue
// ---------------------------------------------------------------------------
#define SM_W   0
#define SM_A   58240
#define SM_SRC 94080
#define SM_DST 94336
#define SM_REL 94592
#define SM_WTB 94848
#define SMEM_EDGE_BYTES 95648
#define ETILE 64
#define ESTR  108   // es row stride in floats (432 B, 16B-aligned, bank-clean)

__device__ __forceinline__ void build_tile(
    char* smb, const float* __restrict__ msg, int ebase, int ne, int tid)
{
    const float* wtb = (const float*)(smb + SM_WTB);   // Wt | bt
    const float* rel = (const float*)(smb + SM_REL);
    for (int idx = tid; idx < ETILE * 34; idx += 256) {
        int r = idx / 34, g = idx - r * 34;
        int j0 = g * 8;
        int eg = ebase + r; if (eg >= ne) eg = ne - 1;
        float v[8];
        if (j0 + 8 <= 100) {
            float rr = rel[r];
            #pragma unroll
            for (int i = 0; i < 8; i++)
                v[i] = __cosf(fmaf(rr, wtb[j0 + i], wtb[100 + j0 + i]));
        } else if (j0 >= 104) {
            const float4* m4 = (const float4*)(msg + (size_t)eg * 172 + (j0 - 100));
            float4 a = m4[0], b = m4[1];
            v[0] = a.x; v[1] = a.y; v[2] = a.z; v[3] = a.w;
            v[4] = b.x; v[5] = b.y; v[6] = b.z; v[7] = b.w;
        } else {
            float rr = rel[r];
            const float* mrow = msg + (size_t)eg * 172;
            #pragma unroll
            for (int i = 0; i < 8; i++) {
                int j = j0 + i;
                v[i] = (j < 100) ? __cosf(fmaf(rr, wtb[j], wtb[100 + j])) : mrow[j - 100];
            }
        }
        uint32_t p[4];
        #pragma unroll
        for (int i = 0; i < 4; i++) {
            __half2 h;
            h.x = __float2half_rn(v[2 * i]);
            h.y = __float2half_rn(v[2 * i + 1]);
            p[i] = *reinterpret_cast<uint32_t*>(&h);
        }
        *(uint4*)(smb + SM_A + r * 560 + j0 * 2) = make_uint4(p[0], p[1], p[2], p[3]);
    }
}

__global__ void __launch_bounds__(256, 2) k_edge(
    const float* __restrict__ lu, const float* __restrict__ t,
    const float* __restrict__ msg,
    const float* __restrict__ Wt, const float* __restrict__ bt,
    const float* __restrict__ We, const int* __restrict__ ei,
    int n, int ne)
{
    extern __shared__ char smb[];
    uint32_t sbase = smem_u32(smb);
    int tid = threadIdx.x;
    int warp = tid >> 5, lane = tid & 31;

    // one-time: W [104 n-rows][272 k] fp16, stride 280; cols>=100 zero
    for (int idx = tid; idx < 104 * 272; idx += 256) {
        int c = idx / 272, j = idx - c * 272;
        float w = (c < 100) ? We[j * 100 + c] : 0.0f;
        *(__half*)(smb + SM_W + c * 560 + j * 2) = __float2half_rn(w);
    }
    {
        float* wtb = (float*)(smb + SM_WTB);
        for (int i = tid; i < 100; i += 256) { wtb[i] = Wt[i]; wtb[100 + i] = bt[i]; }
    }
    __syncthreads();

    int* s_src = (int*)(smb + SM_SRC);
    int* s_dst = (int*)(smb + SM_DST);
    float* s_rel = (float*)(smb + SM_REL);
    float* es = (float*)(smb + SM_A);   // es[64][ESTR] row-major, overlays A
    const float SCALE = 0.14142135623730951f;
    int lq = (lane < 25) ? lane : 24;

    // MMA role: warp w -> M-block (w&3)*16, N-half (w>>2)
    int mrow = (warp & 3) * 16;
    int nf0  = (warp >> 2) * 7;
    int nfe  = (warp >> 2) ? 13 : 7;

    int ntiles = (ne + ETILE - 1) / ETILE;
    for (int tile = blockIdx.x; tile < ntiles; tile += gridDim.x) {
        int ebase = tile * ETILE;
        __syncthreads();   // prev epilogue done before overwriting es/A/meta

        if (tid < ETILE) {
            int eg = ebase + tid;
            bool valid = eg < ne;
            int eidx = valid ? eg : 0;
            int s = ei[eidx], d = ei[ne + eidx];
            s_src[tid] = s; s_dst[tid] = d;
            s_rel[tid] = valid ? (lu[s] - t[eidx]) : 0.0f;
            if (valid) {
                const char* qb = (const char*)(g_nproj + (size_t)d * 400);
                const char* kb = (const char*)(g_nproj + (size_t)s * 400 + 100);
                const char* vb = (const char*)(g_nproj + (size_t)s * 400 + 200);
                #pragma unroll
                for (int o = 0; o < 400; o += 128) {
                    prefetchL2(qb + o); prefetchL2(kb + o); prefetchL2(vb + o);
                }
            }
        }
        __syncthreads();

        build_tile(smb, msg, ebase, ne, tid);   // A fp16
        __syncthreads();

        float acc[7][4];
        #pragma unroll
        for (int nf = 0; nf < 7; nf++) {
            acc[nf][0] = 0.f; acc[nf][1] = 0.f; acc[nf][2] = 0.f; acc[nf][3] = 0.f;
        }

        {
            uint32_t abase = sbase + SM_A
                           + (uint32_t)((mrow + (lane & 15)) * 560 + (lane >> 4) * 16);
            uint32_t af[17][4];
            #pragma unroll
            for (int k = 0; k < 17; k++) ldsm_x4(af[k], abase + k * 32);

            #pragma unroll 1
            for (int nf = nf0; nf < nfe; nf++) {
                float* ac = acc[nf - nf0];
                uint32_t bb = sbase + SM_W
                    + (uint32_t)((nf * 8 + (lane & 7)) * 560 + (lane >> 3) * 16);
                #pragma unroll
                for (int kk = 0; kk < 8; kk++) {
                    uint32_t bh[4];
                    ldsm_x4(bh, bb + kk * 64);
                    mma16816(ac, af[2 * kk],     bh);
                    mma16816(ac, af[2 * kk + 1], bh + 2);
                }
                uint32_t b2[2];
                ldsm_x2(b2, bb + 512);
                mma16816(ac, af[16], b2);
            }
        }
        __syncthreads();   // A ldsm reads done before es overwrite

        {
            int rowA = mrow + (lane >> 2);
            #pragma unroll 1
            for (int nf = nf0; nf < nfe; nf++) {
                float* ac = acc[nf - nf0];
                int col = nf * 8 + 2 * (lane & 3);
                *(float2*)(es + rowA * ESTR + col)       = make_float2(ac[0], ac[1]);
                *(float2*)(es + (rowA + 8) * ESTR + col) = make_float2(ac[2], ac[3]);
            }
        }
        __syncthreads();

        // pair-interleaved epilogue: warp owns edges [warp*8, warp*8+8)
        #pragma unroll 1
        for (int i = 0; i < 8; i += 2) {
            int er0 = warp * 8 + i;
            int er1 = er0 + 1;
            int eg0 = ebase + er0;
            if (eg0 >= ne) break;
            bool v1 = (ebase + er1) < ne;
            int s0 = s_src[er0], d0 = s_dst[er0];
            int s1 = s_src[er1], d1 = s_dst[er1];
            float4 e40 = make_float4(0,0,0,0), e41 = e40;
            float4 q0 = e40, k0 = e40, vv0 = e40;
            float4 q1 = e40, k1 = e40, vv1 = e40;
            float d00 = 0.f, d01 = 0.f, d10 = 0.f, d11 = 0.f;
            if (lane < 25) {
                e40 = *(const float4*)(es + er0 * ESTR + lq * 4);
                e41 = *(const float4*)(es + er1 * ESTR + lq * 4);
                q0  = *(const float4*)(g_nproj + (size_t)d0 * 400 + lq * 4);
                q1  = *(const float4*)(g_nproj + (size_t)d1 * 400 + lq * 4);
                k0  = *(const float4*)(g_nproj + (size_t)s0 * 400 + 100 + lq * 4);
                k1  = *(const float4*)(g_nproj + (size_t)s1 * 400 + 100 + lq * 4);
                vv0 = *(const float4*)(g_nproj + (size_t)s0 * 400 + 200 + lq * 4);
                vv1 = *(const float4*)(g_nproj + (size_t)s1 * 400 + 200 + lq * 4);
                d00 = q0.x * (k0.x + e40.x) + q0.y * (k0.y + e40.y);
                d01 = q0.z * (k0.z + e40.z) + q0.w * (k0.w + e40.w);
                d10 = q1.x * (k1.x + e41.x) + q1.y * (k1.y + e41.y);
                d11 = q1.z * (k1.z + e41.z) + q1.w * (k1.w + e41.w);
            }
            float p00 = ((lane < 13) ? d00 : 0.0f) + ((lane < 12) ? d01 : 0.0f);
            float p01 = ((lane < 13) ? 0.0f : d00) + ((lane < 12) ? 0.0f : d01);
            float p10 = ((lane < 13) ? d10 : 0.0f) + ((lane < 12) ? d11 : 0.0f);
            float p11 = ((lane < 13) ? 0.0f : d10) + ((lane < 12) ? 0.0f : d11);
            #pragma unroll
            for (int o = 16; o > 0; o >>= 1) {
                p00 += __shfl_xor_sync(0xffffffffu, p00, o);
                p01 += __shfl_xor_sync(0xffffffffu, p01, o);
                p10 += __shfl_xor_sync(0xffffffffu, p10, o);
                p11 += __shfl_xor_sync(0xffffffffu, p11, o);
            }
            float ex00 = __expf(p00 * SCALE), ex01 = __expf(p01 * SCALE);
            float ex10 = __expf(p10 * SCALE), ex11 = __expf(p11 * SCALE);
            if (lane == 0) {
                red2(&g_denom[(size_t)d0 * 2], ex00, ex01);
                if (v1) red2(&g_denom[(size_t)d1 * 2], ex10, ex11);
            }
            if (lane < 25) {
                float w00 = (lane < 13) ? ex00 : ex01;
                float w01 = (lane < 12) ? ex00 : ex01;
                red4(g_acc + (size_t)d0 * 100 + lq * 4,
                     w00 * (vv0.x + e40.x), w00 * (vv0.y + e40.y),
                     w01 * (vv0.z + e40.z), w01 * (vv0.w + e40.w));
                if (v1) {
                    float w10 = (lane < 13) ? ex10 : ex11;
                    float w11 = (lane < 12) ? ex10 : ex11;
                    red4(g_acc + (size_t)d1 * 100 + lq * 4,
                         w10 * (vv1.x + e41.x), w10 * (vv1.y + e41.y),
                         w11 * (vv1.z + e41.z), w11 * (vv1.w + e41.w));
                }
            }
        }
    }
}

// ---------------------------------------------------------------------------
__global__ void k_final(float* __restrict__ out, int n) {
    int tot = n * 25;
    for (int i = blockIdx.x * blockDim.x + threadIdx.x; i < tot;
         i += gridDim.x * blockDim.x) {
        int nd = i / 25, q = i % 25;
        float den0 = g_denom[(size_t)nd * 2 + 0];
        float den1 = g_denom[(size_t)nd * 2 + 1];
        float dxy = (q < 13) ? den0 : den1;
        float dzw = (q < 12) ? den0 : den1;
        float rxy = (dxy > 0.0f) ? (1.0f / dxy) : 0.0f;
        float rzw = (dzw > 0.0f) ? (1.0f / dzw) : 0.0f;
        float4 a4 = ((const float4*)g_acc)[i];
        float4 sk = *(const float4*)(g_nproj + (size_t)nd * 400 + 300 + q * 4);
        float4 o;
        o.x = a4.x * rxy + sk.x;
        o.y = a4.y * rxy + sk.y;
        o.z = a4.z * rzw + sk.z;
        o.w = a4.w * rzw + sk.w;
        ((float4*)out)[i] = o;
    }
}

// ---------------------------------------------------------------------------
extern "C" void kernel_launch(void* const* d_in, const int* in_sizes, int n_in,
                              void* d_out, int out_size) {
    const float* x   = (const float*)d_in[0];
    const float* lu  = (const float*)d_in[1];
    const float* t   = (const float*)d_in[2];
    const float* msg = (const float*)d_in[3];
    const float* Wt  = (const float*)d_in[4];
    const float* bt  = (const float*)d_in[5];
    const float* Wq  = (const float*)d_in[6];
    const float* bq  = (const float*)d_in[7];
    const float* Wk  = (const float*)d_in[8];
    const float* bk  = (const float*)d_in[9];
    const float* Wv  = (const float*)d_in[10];
    const float* bv  = (const float*)d_in[11];
    const float* We  = (const float*)d_in[12];
    const float* Ws  = (const float*)d_in[13];
    const float* bs  = (const float*)d_in[14];
    const int*   ei  = (const int*)d_in[15];

    int n  = in_sizes[1];
    int ne = in_sizes[2];
    float* out = (float*)d_out;

    int dev = 0;
    cudaGetDevice(&dev);
    int nsm = 148;
    cudaDeviceGetAttribute(&nsm, cudaDevAttrMultiProcessorCount, dev);

    size_t smem1 = (size_t)(40000 + 400 + 12 * 400) * 4;
    cudaFuncSetAttribute(k_nproj, cudaFuncAttributeMaxDynamicSharedMemorySize, (int)smem1);
    cudaFuncSetAttribute(k_edge,  cudaFuncAttributeMaxDynamicSharedMemorySize, SMEM_EDGE_BYTES);

    k_zero<<<2048, 256>>>(n);
    k_nproj<<<nsm, 384, smem1>>>(x, Wq, bq, Wk, bk, Wv, bv, Ws, bs, n);
    k_edge<<<nsm * 2, 256, SMEM_EDGE_BYTES>>>(lu, t, msg, Wt, bt, We, ei, n, ne);
    k_final<<<4096, 256>>>(out, n);
}

// round 11
// speedup vs baseline: 1.8903x; 1.1535x over previous
#include <cuda_runtime.h>
#include <cuda_fp16.h>
#include <cstdint>

#define HC 100
typedef unsigned long long ull;

__device__ float g_nproj[(size_t)100000 * 400];
__device__ float g_acc[(size_t)100000 * HC];
__device__ float g_denom[(size_t)100000 * 2];

__device__ __forceinline__ void red2(float* p, float a, float b) {
    asm volatile("red.global.add.v2.f32 [%0], {%1, %2};" :: "l"(p), "f"(a), "f"(b) : "memory");
}
__device__ __forceinline__ void red4(float* p, float a, float b, float c, float d) {
    asm volatile("red.global.add.v4.f32 [%0], {%1, %2, %3, %4};"
                 :: "l"(p), "f"(a), "f"(b), "f"(c), "f"(d) : "memory");
}
__device__ __forceinline__ void prefetchL2(const void* p) {
    asm volatile("prefetch.global.L2 [%0];" :: "l"(p));
}
__device__ __forceinline__ uint32_t smem_u32(const void* p) {
    uint32_t a;
    asm("{ .reg .u64 t; cvta.to.shared.u64 t, %1; cvt.u32.u64 %0, t; }" : "=r"(a) : "l"(p));
    return a;
}
__device__ __forceinline__ void ldsm_x4(uint32_t* r, uint32_t a) {
    asm volatile("ldmatrix.sync.aligned.m8n8.x4.shared.b16 {%0,%1,%2,%3}, [%4];"
                 : "=r"(r[0]), "=r"(r[1]), "=r"(r[2]), "=r"(r[3]) : "r"(a));
}
__device__ __forceinline__ void ldsm_x2(uint32_t* r, uint32_t a) {
    asm volatile("ldmatrix.sync.aligned.m8n8.x2.shared.b16 {%0,%1}, [%2];"
                 : "=r"(r[0]), "=r"(r[1]) : "r"(a));
}
__device__ __forceinline__ void mma16816(float* c, const uint32_t* a, const uint32_t* b) {
    asm volatile("mma.sync.aligned.m16n8k16.row.col.f32.f16.f16.f32 "
                 "{%0,%1,%2,%3}, {%4,%5,%6,%7}, {%8,%9}, {%0,%1,%2,%3};"
                 : "+f"(c[0]), "+f"(c[1]), "+f"(c[2]), "+f"(c[3])
                 : "r"(a[0]), "r"(a[1]), "r"(a[2]), "r"(a[3]), "r"(b[0]), "r"(b[1]));
}

// ---------------------------------------------------------------------------
// Node projections: HMMA fp16.  g_nproj[nd][0:400] = x[nd] @ [Wq|Wk|Wv|Ws] + b
// 64-node tiles, 2 CTAs/SM. Also zeroes g_acc/g_denom (folded k_zero).
// NPSTR=240 (multiple of 16 for ldmatrix; 60-word rows, conflict-free LDSM)
// ---------------------------------------------------------------------------
#define NP_W   0        // W fp16: 400 rows x 240 B stride
#define NP_B   96000    // bias: 400 floats
#define NP_A   97600    // A fp16: 64 rows x 240 B
#define SMEM_NP_BYTES 112960
#define NPSTR  240

__global__ void __launch_bounds__(256, 2) k_nproj(
    const float* __restrict__ x,
    const float* __restrict__ Wq, const float* __restrict__ bq,
    const float* __restrict__ Wk, const float* __restrict__ bk,
    const float* __restrict__ Wv, const float* __restrict__ bv,
    const float* __restrict__ Ws, const float* __restrict__ bs,
    int n)
{
    extern __shared__ char smb[];
    uint32_t sbase = smem_u32(smb);
    int tid = threadIdx.x;
    int warp = tid >> 5, lane = tid & 31;
    int gtid = blockIdx.x * 256 + tid;
    int gstep = gridDim.x * 256;

    // fold-in: zero accumulators (disjoint memory; independent of GEMM)
    {
        int na = n * 25;
        int tot = na + n;
        float4 z4 = make_float4(0.f, 0.f, 0.f, 0.f);
        for (int i = gtid; i < tot; i += gstep) {
            if (i < na) ((float4*)g_acc)[i] = z4;
            else        ((float2*)g_denom)[i - na] = make_float2(0.f, 0.f);
        }
    }

    // one-time: W fp16 [400 out-cols as rows][100 k cols + pad], bias
    for (int idx = tid; idx < 400 * 100; idx += 256) {
        int c = idx / 100, j = idx - c * 100;
        float v;
        if      (c < 100) v = Wq[j * 100 + c];
        else if (c < 200) v = Wk[j * 100 + c - 100];
        else if (c < 300) v = Wv[j * 100 + c - 200];
        else              v = Ws[j * 100 + c - 300];
        *(__half*)(smb + NP_W + c * NPSTR + j * 2) = __float2half_rn(v);
    }
    for (int idx = tid; idx < 400 * 10; idx += 256) {   // zero pad bytes 200..240
        int c = idx / 10, z = idx - c * 10;
        *(uint32_t*)(smb + NP_W + c * NPSTR + 200 + z * 4) = 0u;
    }
    {
        float* bsm = (float*)(smb + NP_B);
        for (int i = tid; i < 400; i += 256) {
            bsm[i] = (i < 100) ? bq[i] : (i < 200) ? bk[i - 100]
                   : (i < 300) ? bv[i - 200] : bs[i - 300];
        }
    }
    __syncthreads();

    const float* bsm = (const float*)(smb + NP_B);
    int mrow = (warp & 3) * 16;
    int nfbase = (warp >> 2) * 25;

    int ntiles = (n + 63) >> 6;
    for (int tile = blockIdx.x; tile < ntiles; tile += gridDim.x) {
        int nbase = tile << 6;
        __syncthreads();   // prev tile's A reads done

        // build A tile: 64 rows x 100 fp16 (+pad) from x
        for (int idx = tid; idx < 64 * 25; idx += 256) {
            int r = idx / 25, q = idx - r * 25;
            int nd = nbase + r; if (nd >= n) nd = n - 1;
            float4 v = ((const float4*)(x + (size_t)nd * 100))[q];
            __half2 h0, h1;
            h0.x = __float2half_rn(v.x); h0.y = __float2half_rn(v.y);
            h1.x = __float2half_rn(v.z); h1.y = __float2half_rn(v.w);
            uint2 p;
            p.x = *reinterpret_cast<uint32_t*>(&h0);
            p.y = *reinterpret_cast<uint32_t*>(&h1);
            *(uint2*)(smb + NP_A + r * NPSTR + q * 8) = p;
        }
        for (int idx = tid; idx < 64 * 10; idx += 256) {   // pad bytes 200..240
            int r = idx / 10, z = idx - r * 10;
            *(uint32_t*)(smb + NP_A + r * NPSTR + 200 + z * 4) = 0u;
        }
        __syncthreads();

        uint32_t abase = sbase + NP_A
                       + (uint32_t)((mrow + (lane & 15)) * NPSTR + (lane >> 4) * 16);
        uint32_t af[7][4];
        #pragma unroll
        for (int k = 0; k < 7; k++) ldsm_x4(af[k], abase + k * 32);

        int rowA = mrow + (lane >> 2);
        int nd0 = nbase + rowA;
        int nd1 = nd0 + 8;

        #pragma unroll 1
        for (int nf = 0; nf < 25; nf++) {
            int nfg = nfbase + nf;
            uint32_t bb = sbase + NP_W
                + (uint32_t)((nfg * 8 + (lane & 7)) * NPSTR + (lane >> 3) * 16);
            float ac[4] = {0.f, 0.f, 0.f, 0.f};
            #pragma unroll
            for (int kk = 0; kk < 3; kk++) {
                uint32_t bh[4];
                ldsm_x4(bh, bb + kk * 64);
                mma16816(ac, af[2 * kk],     bh);
                mma16816(ac, af[2 * kk + 1], bh + 2);
            }
            uint32_t b2[2];
            ldsm_x2(b2, bb + 192);
            mma16816(ac, af[6], b2);

            int col = nfg * 8 + 2 * (lane & 3);
            float bx = bsm[col], by = bsm[col + 1];
            if (nd0 < n)
                *(float2*)(g_nproj + (size_t)nd0 * 400 + col) =
                    make_float2(ac[0] + bx, ac[1] + by);
            if (nd1 < n)
                *(float2*)(g_nproj + (size_t)nd1 * 400 + col) =
                    make_float2(ac[2] + bx, ac[3] + by);
        }
    }
}

// ---------------------------------------------------------------------------
// Edge kernel: HMMA fp16 single-pass GEMM, 64-edge tiles, 2 CTAs/SM,
// row-major es + pair-interleaved epilogue (unchanged from R9)
// ---------------------------------------------------------------------------
#define SM_W   0
#define SM_A   58240
#define SM_SRC 94080
#define SM_DST 94336
#define SM_REL 94592
#define SM_WTB 94848
#define SMEM_EDGE_BYTES 95648
#define ETILE 64
#define ESTR  108

__device__ __forceinline__ void build_tile(
    char* smb, const float* __restrict__ msg, int ebase, int ne, int tid)
{
    const float* wtb = (const float*)(smb + SM_WTB);
    const float* rel = (const float*)(smb + SM_REL);
    for (int idx = tid; idx < ETILE * 34; idx += 256) {
        int r = idx / 34, g = idx - r * 34;
        int j0 = g * 8;
        int eg = ebase + r; if (eg >= ne) eg = ne - 1;
        float v[8];
        if (j0 + 8 <= 100) {
            float rr = rel[r];
            #pragma unroll
            for (int i = 0; i < 8; i++)
                v[i] = __cosf(fmaf(rr, wtb[j0 + i], wtb[100 + j0 + i]));
        } else if (j0 >= 104) {
            const float4* m4 = (const float4*)(msg + (size_t)eg * 172 + (j0 - 100));
            float4 a = m4[0], b = m4[1];
            v[0] = a.x; v[1] = a.y; v[2] = a.z; v[3] = a.w;
            v[4] = b.x; v[5] = b.y; v[6] = b.z; v[7] = b.w;
        } else {
            float rr = rel[r];
            const float* mrow = msg + (size_t)eg * 172;
            #pragma unroll
            for (int i = 0; i < 8; i++) {
                int j = j0 + i;
                v[i] = (j < 100) ? __cosf(fmaf(rr, wtb[j], wtb[100 + j])) : mrow[j - 100];
            }
        }
        uint32_t p[4];
        #pragma unroll
        for (int i = 0; i < 4; i++) {
            __half2 h;
            h.x = __float2half_rn(v[2 * i]);
            h.y = __float2half_rn(v[2 * i + 1]);
            p[i] = *reinterpret_cast<uint32_t*>(&h);
        }
        *(uint4*)(smb + SM_A + r * 560 + j0 * 2) = make_uint4(p[0], p[1], p[2], p[3]);
    }
}

__global__ void __launch_bounds__(256, 2) k_edge(
    const float* __restrict__ lu, const float* __restrict__ t,
    const float* __restrict__ msg,
    const float* __restrict__ Wt, const float* __restrict__ bt,
    const float* __restrict__ We, const int* __restrict__ ei,
    int n, int ne)
{
    extern __shared__ char smb[];
    uint32_t sbase = smem_u32(smb);
    int tid = threadIdx.x;
    int warp = tid >> 5, lane = tid & 31;

    for (int idx = tid; idx < 104 * 272; idx += 256) {
        int c = idx / 272, j = idx - c * 272;
        float w = (c < 100) ? We[j * 100 + c] : 0.0f;
        *(__half*)(smb + SM_W + c * 560 + j * 2) = __float2half_rn(w);
    }
    {
        float* wtb = (float*)(smb + SM_WTB);
        for (int i = tid; i < 100; i += 256) { wtb[i] = Wt[i]; wtb[100 + i] = bt[i]; }
    }
    __syncthreads();

    int* s_src = (int*)(smb + SM_SRC);
    int* s_dst = (int*)(smb + SM_DST);
    float* s_rel = (float*)(smb + SM_REL);
    float* es = (float*)(smb + SM_A);
    const float SCALE = 0.14142135623730951f;
    int lq = (lane < 25) ? lane : 24;

    int mrow = (warp & 3) * 16;
    int nf0  = (warp >> 2) * 7;
    int nfe  = (warp >> 2) ? 13 : 7;

    int ntiles = (ne + ETILE - 1) / ETILE;
    for (int tile = blockIdx.x; tile < ntiles; tile += gridDim.x) {
        int ebase = tile * ETILE;
        __syncthreads();

        if (tid < ETILE) {
            int eg = ebase + tid;
            bool valid = eg < ne;
            int eidx = valid ? eg : 0;
            int s = ei[eidx], d = ei[ne + eidx];
            s_src[tid] = s; s_dst[tid] = d;
            s_rel[tid] = valid ? (lu[s] - t[eidx]) : 0.0f;
            if (valid) {
                const char* qb = (const char*)(g_nproj + (size_t)d * 400);
                const char* kb = (const char*)(g_nproj + (size_t)s * 400 + 100);
                const char* vb = (const char*)(g_nproj + (size_t)s * 400 + 200);
                #pragma unroll
                for (int o = 0; o < 400; o += 128) {
                    prefetchL2(qb + o); prefetchL2(kb + o); prefetchL2(vb + o);
                }
            }
        }
        __syncthreads();

        build_tile(smb, msg, ebase, ne, tid);
        __syncthreads();

        float acc[7][4];
        #pragma unroll
        for (int nf = 0; nf < 7; nf++) {
            acc[nf][0] = 0.f; acc[nf][1] = 0.f; acc[nf][2] = 0.f; acc[nf][3] = 0.f;
        }

        {
            uint32_t abase = sbase + SM_A
                           + (uint32_t)((mrow + (lane & 15)) * 560 + (lane >> 4) * 16);
            uint32_t af[17][4];
            #pragma unroll
            for (int k = 0; k < 17; k++) ldsm_x4(af[k], abase + k * 32);

            #pragma unroll 1
            for (int nf = nf0; nf < nfe; nf++) {
                float* ac = acc[nf - nf0];
                uint32_t bb = sbase + SM_W
                    + (uint32_t)((nf * 8 + (lane & 7)) * 560 + (lane >> 3) * 16);
                #pragma unroll
                for (int kk = 0; kk < 8; kk++) {
                    uint32_t bh[4];
                    ldsm_x4(bh, bb + kk * 64);
                    mma16816(ac, af[2 * kk],     bh);
                    mma16816(ac, af[2 * kk + 1], bh + 2);
                }
                uint32_t b2[2];
                ldsm_x2(b2, bb + 512);
                mma16816(ac, af[16], b2);
            }
        }
        __syncthreads();

        {
            int rowA = mrow + (lane >> 2);
            #pragma unroll 1
            for (int nf = nf0; nf < nfe; nf++) {
                float* ac = acc[nf - nf0];
                int col = nf * 8 + 2 * (lane & 3);
                *(float2*)(es + rowA * ESTR + col)       = make_float2(ac[0], ac[1]);
                *(float2*)(es + (rowA + 8) * ESTR + col) = make_float2(ac[2], ac[3]);
            }
        }
        __syncthreads();

        #pragma unroll 1
        for (int i = 0; i < 8; i += 2) {
            int er0 = warp * 8 + i;
            int er1 = er0 + 1;
            int eg0 = ebase + er0;
            if (eg0 >= ne) break;
            bool v1 = (ebase + er1) < ne;
            int s0 = s_src[er0], d0 = s_dst[er0];
            int s1 = s_src[er1], d1 = s_dst[er1];
            float4 e40 = make_float4(0,0,0,0), e41 = e40;
            float4 q0 = e40, k0 = e40, vv0 = e40;
            float4 q1 = e40, k1 = e40, vv1 = e40;
            float d00 = 0.f, d01 = 0.f, d10 = 0.f, d11 = 0.f;
            if (lane < 25) {
                e40 = *(const float4*)(es + er0 * ESTR + lq * 4);
                e41 = *(const float4*)(es + er1 * ESTR + lq * 4);
                q0  = *(const float4*)(g_nproj + (size_t)d0 * 400 + lq * 4);
                q1  = *(const float4*)(g_nproj + (size_t)d1 * 400 + lq * 4);
                k0  = *(const float4*)(g_nproj + (size_t)s0 * 400 + 100 + lq * 4);
                k1  = *(const float4*)(g_nproj + (size_t)s1 * 400 + 100 + lq * 4);
                vv0 = *(const float4*)(g_nproj + (size_t)s0 * 400 + 200 + lq * 4);
                vv1 = *(const float4*)(g_nproj + (size_t)s1 * 400 + 200 + lq * 4);
                d00 = q0.x * (k0.x + e40.x) + q0.y * (k0.y + e40.y);
                d01 = q0.z * (k0.z + e40.z) + q0.w * (k0.w + e40.w);
                d10 = q1.x * (k1.x + e41.x) + q1.y * (k1.y + e41.y);
                d11 = q1.z * (k1.z + e41.z) + q1.w * (k1.w + e41.w);
            }
            float p00 = ((lane < 13) ? d00 : 0.0f) + ((lane < 12) ? d01 : 0.0f);
            float p01 = ((lane < 13) ? 0.0f : d00) + ((lane < 12) ? 0.0f : d01);
            float p10 = ((lane < 13) ? d10 : 0.0f) + ((lane < 12) ? d11 : 0.0f);
            float p11 = ((lane < 13) ? 0.0f : d10) + ((lane < 12) ? 0.0f : d11);
            #pragma unroll
            for (int o = 16; o > 0; o >>= 1) {
                p00 += __shfl_xor_sync(0xffffffffu, p00, o);
                p01 += __shfl_xor_sync(0xffffffffu, p01, o);
                p10 += __shfl_xor_sync(0xffffffffu, p10, o);
                p11 += __shfl_xor_sync(0xffffffffu, p11, o);
            }
            float ex00 = __expf(p00 * SCALE), ex01 = __expf(p01 * SCALE);
            float ex10 = __expf(p10 * SCALE), ex11 = __expf(p11 * SCALE);
            if (lane == 0) {
                red2(&g_denom[(size_t)d0 * 2], ex00, ex01);
                if (v1) red2(&g_denom[(size_t)d1 * 2], ex10, ex11);
            }
            if (lane < 25) {
                float w00 = (lane < 13) ? ex00 : ex01;
                float w01 = (lane < 12) ? ex00 : ex01;
                red4(g_acc + (size_t)d0 * 100 + lq * 4,
                     w00 * (vv0.x + e40.x), w00 * (vv0.y + e40.y),
                     w01 * (vv0.z + e40.z), w01 * (vv0.w + e40.w));
                if (v1) {
                    float w10 = (lane < 13) ? ex10 : ex11;
                    float w11 = (lane < 12) ? ex10 : ex11;
                    red4(g_acc + (size_t)d1 * 100 + lq * 4,
                         w10 * (vv1.x + e41.x), w10 * (vv1.y + e41.y),
                         w11 * (vv1.z + e41.z), w11 * (vv1.w + e41.w));
                }
            }
        }
    }
}

// ---------------------------------------------------------------------------
__global__ void k_final(float* __restrict__ out, int n) {
    int tot = n * 25;
    for (int i = blockIdx.x * blockDim.x + threadIdx.x; i < tot;
         i += gridDim.x * blockDim.x) {
        int nd = i / 25, q = i % 25;
        float den0 = g_denom[(size_t)nd * 2 + 0];
        float den1 = g_denom[(size_t)nd * 2 + 1];
        float dxy = (q < 13) ? den0 : den1;
        float dzw = (q < 12) ? den0 : den1;
        float rxy = (dxy > 0.0f) ? (1.0f / dxy) : 0.0f;
        float rzw = (dzw > 0.0f) ? (1.0f / dzw) : 0.0f;
        float4 a4 = ((const float4*)g_acc)[i];
        float4 sk = *(const float4*)(g_nproj + (size_t)nd * 400 + 300 + q * 4);
        float4 o;
        o.x = a4.x * rxy + sk.x;
        o.y = a4.y * rxy + sk.y;
        o.z = a4.z * rzw + sk.z;
        o.w = a4.w * rzw + sk.w;
        ((float4*)out)[i] = o;
    }
}

// ---------------------------------------------------------------------------
extern "C" void kernel_launch(void* const* d_in, const int* in_sizes, int n_in,
                              void* d_out, int out_size) {
    const float* x   = (const float*)d_in[0];
    const float* lu  = (const float*)d_in[1];
    const float* t   = (const float*)d_in[2];
    const float* msg = (const float*)d_in[3];
    const float* Wt  = (const float*)d_in[4];
    const float* bt  = (const float*)d_in[5];
    const float* Wq  = (const float*)d_in[6];
    const float* bq  = (const float*)d_in[7];
    const float* Wk  = (const float*)d_in[8];
    const float* bk  = (const float*)d_in[9];
    const float* Wv  = (const float*)d_in[10];
    const float* bv  = (const float*)d_in[11];
    const float* We  = (const float*)d_in[12];
    const float* Ws  = (const float*)d_in[13];
    const float* bs  = (const float*)d_in[14];
    const int*   ei  = (const int*)d_in[15];

    int n  = in_sizes[1];
    int ne = in_sizes[2];
    float* out = (float*)d_out;

    int dev = 0;
    cudaGetDevice(&dev);
    int nsm = 148;
    cudaDeviceGetAttribute(&nsm, cudaDevAttrMultiProcessorCount, dev);

    cudaFuncSetAttribute(k_nproj, cudaFuncAttributeMaxDynamicSharedMemorySize, SMEM_NP_BYTES);
    cudaFuncSetAttribute(k_edge,  cudaFuncAttributeMaxDynamicSharedMemorySize, SMEM_EDGE_BYTES);

    k_nproj<<<nsm * 2, 256, SMEM_NP_BYTES>>>(x, Wq, bq, Wk, bk, Wv, bv, Ws, bs, n);
    k_edge<<<nsm * 2, 256, SMEM_EDGE_BYTES>>>(lu, t, msg, Wt, bt, We, ei, n, ne);
    k_final<<<4096, 256>>>(out, n);
}